// round 2
// baseline (speedup 1.0000x reference)
#include <cuda_runtime.h>
#include <cuda_bf16.h>
#include <cstdint>

// Problem constants
static constexpr int BB = 1024;   // batch
static constexpr int NI = 2048;
static constexpr int NH = 4096;
static constexpr int NO = 1024;
static constexpr int CC = 4;      // LSTM cell size

// Scratch for aggregated pre-activations (no cudaMalloc allowed)
__device__ float g_inh[(size_t)BB * NH];
__device__ float g_ino[(size_t)BB * NO];

// ---------------------------------------------------------------------------
// GEMM: out[m,n] = relu( sum_k A1[m,k<K1]*W1[n,k] + A2[m,k<K2]*W2[n,k]
//                        + bias1[n] + bias2[n] )
// A1:[M,K1], A2:[M,K2], W1:[N,K1], W2:[N,K2] all row-major (K contiguous).
// Tile 128x128, BK=16, 256 threads, 8x8 per-thread register block.
// ---------------------------------------------------------------------------
#define GBM 128
#define GBN 128
#define GBK 16

__global__ __launch_bounds__(256) void gemm2_relu(
    const float* __restrict__ A1, const float* __restrict__ A2,
    const float* __restrict__ W1, const float* __restrict__ W2,
    const float* __restrict__ bias1, const float* __restrict__ bias2,
    float* __restrict__ out, int M, int N, int K1, int K2)
{
    __shared__ float As[GBK][GBM + 4];
    __shared__ float Bs[GBK][GBN + 4];

    const int tid = threadIdx.x;
    const int tx = tid & 15;        // 0..15 -> n direction
    const int ty = tid >> 4;        // 0..15 -> m direction
    const int m0 = blockIdx.y * GBM;
    const int n0 = blockIdx.x * GBN;

    float acc[8][8];
#pragma unroll
    for (int i = 0; i < 8; ++i)
#pragma unroll
        for (int j = 0; j < 8; ++j) acc[i][j] = 0.f;

    const int Ktot = K1 + K2;
    for (int k0 = 0; k0 < Ktot; k0 += GBK) {
        const float* Ap; const float* Wp; int lda, ko;
        if (k0 < K1) { Ap = A1; Wp = W1; lda = K1; ko = k0; }
        else         { Ap = A2; Wp = W2; lda = K2; ko = k0 - K1; }

        // Load 128x16 A tile and 128x16 W tile (float4 along K)
#pragma unroll
        for (int j = 0; j < 2; ++j) {
            int v   = tid + 256 * j;          // 0..511
            int row = v >> 2;                 // 0..127
            int kv  = (v & 3) * 4;            // 0,4,8,12
            float4 ta = *(const float4*)&Ap[(size_t)(m0 + row) * lda + ko + kv];
            As[kv + 0][row] = ta.x; As[kv + 1][row] = ta.y;
            As[kv + 2][row] = ta.z; As[kv + 3][row] = ta.w;
            float4 tw = *(const float4*)&Wp[(size_t)(n0 + row) * lda + ko + kv];
            Bs[kv + 0][row] = tw.x; Bs[kv + 1][row] = tw.y;
            Bs[kv + 2][row] = tw.z; Bs[kv + 3][row] = tw.w;
        }
        __syncthreads();

#pragma unroll
        for (int kk = 0; kk < GBK; ++kk) {
            float a[8], b[8];
            *(float4*)&a[0] = *(const float4*)&As[kk][ty * 8];
            *(float4*)&a[4] = *(const float4*)&As[kk][ty * 8 + 4];
            *(float4*)&b[0] = *(const float4*)&Bs[kk][tx * 8];
            *(float4*)&b[4] = *(const float4*)&Bs[kk][tx * 8 + 4];
#pragma unroll
            for (int i = 0; i < 8; ++i)
#pragma unroll
                for (int j = 0; j < 8; ++j)
                    acc[i][j] = fmaf(a[i], b[j], acc[i][j]);
        }
        __syncthreads();
    }

    // Fused bias + ReLU epilogue, vectorized stores
    float bsum[8];
#pragma unroll
    for (int j = 0; j < 8; ++j) {
        int n = n0 + tx * 8 + j;
        bsum[j] = bias1[n] + bias2[n];
    }
#pragma unroll
    for (int i = 0; i < 8; ++i) {
        int m = m0 + ty * 8 + i;
#pragma unroll
        for (int jv = 0; jv < 2; ++jv) {
            float4 r;
            r.x = fmaxf(acc[i][jv * 4 + 0] + bsum[jv * 4 + 0], 0.f);
            r.y = fmaxf(acc[i][jv * 4 + 1] + bsum[jv * 4 + 1], 0.f);
            r.z = fmaxf(acc[i][jv * 4 + 2] + bsum[jv * 4 + 2], 0.f);
            r.w = fmaxf(acc[i][jv * 4 + 3] + bsum[jv * 4 + 3], 0.f);
            *(float4*)&out[(size_t)m * N + n0 + tx * 8 + jv * 4] = r;
        }
    }
}

// ---------------------------------------------------------------------------
// Per-node LSTM pointwise step.
//   xin, hprev : [B, N]          (n contiguous)
//   cprev      : [N, B, 4]       (c contiguous, then b)
//   Wih/Whh/bias: [N, 16], Whr: [N, 4]
//   hnew : [B, N], cnew : [N, B, 4]
// Block processes 32 nodes x 32 batch. smem transposes keep all gmem accesses
// coalesced: [B,N] arrays touched n-fastest, [N,B,4] arrays touched b-fastest.
// ---------------------------------------------------------------------------
__global__ __launch_bounds__(256) void lstm_pointwise(
    const float* __restrict__ xin, const float* __restrict__ hprev,
    const float* __restrict__ cprev,
    const float* __restrict__ Wih, const float* __restrict__ Whh,
    const float* __restrict__ bias, const float* __restrict__ Whr,
    float* __restrict__ hnew, float* __restrict__ cnew,
    int N, int B)
{
    __shared__ float sX[32][33];
    __shared__ float sH[32][33];
    __shared__ float sHn[32][33];
    __shared__ float sWih[32][16];
    __shared__ float sWhh[32][16];
    __shared__ float sBias[32][16];
    __shared__ float sWhr[32][4];

    const int t = threadIdx.x;
    const int n0 = blockIdx.x * 32;
    const int b0 = blockIdx.y * 32;

    // Load per-node weights (float4 per thread)
    if (t < 128) {
        int nl = t >> 2, w = t & 3;
        ((float4*)&sWih[nl][0])[w]  = ((const float4*)Wih)[(size_t)(n0 + nl) * 4 + w];
        ((float4*)&sWhh[nl][0])[w]  = ((const float4*)Whh)[(size_t)(n0 + nl) * 4 + w];
        ((float4*)&sBias[nl][0])[w] = ((const float4*)bias)[(size_t)(n0 + nl) * 4 + w];
    }
    if (t < 32) {
        *(float4*)&sWhr[t][0] = ((const float4*)Whr)[(size_t)(n0 + t)];
    }

    // Load x and h_prev tiles, coalesced (n fastest)
#pragma unroll
    for (int q = 0; q < 4; ++q) {
        int idx = t + 256 * q;
        int bl = idx >> 5, nl = idx & 31;
        sX[bl][nl] = xin  [(size_t)(b0 + bl) * N + n0 + nl];
        sH[bl][nl] = hprev[(size_t)(b0 + bl) * N + n0 + nl];
    }
    __syncthreads();

    // Compute, b fastest so the [N,B,4] cell accesses are coalesced float4s
#pragma unroll
    for (int q = 0; q < 4; ++q) {
        int idx = t + 256 * q;
        int bl = idx & 31, nl = idx >> 5;
        int n = n0 + nl, b = b0 + bl;

        float x  = sX[bl][nl];
        float hp = sH[bl][nl];

        float g[16];
#pragma unroll
        for (int j = 0; j < 16; ++j)
            g[j] = fmaf(x, sWih[nl][j], fmaf(hp, sWhh[nl][j], sBias[nl][j]));

        float cp[4];
        *(float4*)cp = *(const float4*)&cprev[((size_t)n * B + b) * 4];

        float cn[4];
        float hsum = 0.f;
#pragma unroll
        for (int c = 0; c < 4; ++c) {
            float ig = 1.f / (1.f + expf(-g[c]));
            float fg = 1.f / (1.f + expf(-g[4 + c]));
            float gg = tanhf(g[8 + c]);
            float og = 1.f / (1.f + expf(-g[12 + c]));
            float cnc = fmaf(fg, cp[c], ig * gg);
            cn[c] = cnc;
            hsum = fmaf(og * tanhf(cnc), sWhr[nl][c], hsum);
        }
        *(float4*)&cnew[((size_t)n * B + b) * 4] =
            make_float4(cn[0], cn[1], cn[2], cn[3]);
        sHn[bl][nl] = hsum;
    }
    __syncthreads();

    // Store h_new coalesced (n fastest)
#pragma unroll
    for (int q = 0; q < 4; ++q) {
        int idx = t + 256 * q;
        int bl = idx >> 5, nl = idx & 31;
        hnew[(size_t)(b0 + bl) * N + n0 + nl] = sHn[bl][nl];
    }
}

// ---------------------------------------------------------------------------
// Launch
// ---------------------------------------------------------------------------
extern "C" void kernel_launch(void* const* d_in, const int* in_sizes, int n_in,
                              void* d_out, int out_size)
{
    const float* i_in    = (const float*)d_in[0];
    const float* h_in    = (const float*)d_in[1];
    const float* o_in    = (const float*)d_in[2];
    const float* h_cells = (const float*)d_in[3];
    const float* o_cells = (const float*)d_in[4];
    const float* W_i2h   = (const float*)d_in[5];
    const float* b_i2h   = (const float*)d_in[6];
    const float* W_h2h   = (const float*)d_in[7];
    const float* b_h2h   = (const float*)d_in[8];
    const float* W_i2o   = (const float*)d_in[9];
    const float* b_i2o   = (const float*)d_in[10];
    const float* W_h2o   = (const float*)d_in[11];
    const float* b_h2o   = (const float*)d_in[12];
    const float* Wih_h   = (const float*)d_in[13];
    const float* Whh_h   = (const float*)d_in[14];
    const float* bias_h  = (const float*)d_in[15];
    const float* Whr_h   = (const float*)d_in[16];
    const float* Wih_o   = (const float*)d_in[17];
    const float* Whh_o   = (const float*)d_in[18];
    const float* bias_o  = (const float*)d_in[19];
    const float* Whr_o   = (const float*)d_in[20];

    float* out    = (float*)d_out;
    float* new_h  = out;                                   // [B, NH]
    float* new_o  = new_h + (size_t)BB * NH;               // [B, NO]
    float* new_hc = new_o + (size_t)BB * NO;               // [NH, B, 4]
    float* new_oc = new_hc + (size_t)NH * BB * CC;         // [NO, B, 4]

    float* inh = nullptr;
    float* ino = nullptr;
    cudaGetSymbolAddress((void**)&inh, g_inh);
    cudaGetSymbolAddress((void**)&ino, g_ino);

    // Aggregation GEMMs (fused dual-input, bias, ReLU)
    gemm2_relu<<<dim3(NH / GBN, BB / GBM), 256>>>(
        i_in, h_in, W_i2h, W_h2h, b_i2h, b_h2h, inh, BB, NH, NI, NH);
    gemm2_relu<<<dim3(NO / GBN, BB / GBM), 256>>>(
        i_in, h_in, W_i2o, W_h2o, b_i2o, b_h2o, ino, BB, NO, NI, NH);

    // Per-node LSTM steps
    lstm_pointwise<<<dim3(NH / 32, BB / 32), 256>>>(
        inh, h_in, h_cells, Wih_h, Whh_h, bias_h, Whr_h, new_h, new_hc, NH, BB);
    lstm_pointwise<<<dim3(NO / 32, BB / 32), 256>>>(
        ino, o_in, o_cells, Wih_o, Whh_o, bias_o, Whr_o, new_o, new_oc, NO, BB);
}

// round 5
// speedup vs baseline: 2.3794x; 2.3794x over previous
#include <cuda_runtime.h>
#include <cuda_bf16.h>
#include <cstdint>

// Problem constants
static constexpr int BB = 1024;   // batch
static constexpr int NI = 2048;
static constexpr int NH = 4096;
static constexpr int NO = 1024;
static constexpr int CC = 4;      // LSTM cell size

// ---------------------------------------------------------------------------
// Device scratch (no cudaMalloc allowed)
// ---------------------------------------------------------------------------
__device__ float g_inh[(size_t)BB * NH];
__device__ float g_ino[(size_t)BB * NO];

__device__ __align__(16) __nv_bfloat16 g_i_hi[(size_t)BB * NI];
__device__ __align__(16) __nv_bfloat16 g_i_lo[(size_t)BB * NI];
__device__ __align__(16) __nv_bfloat16 g_h_hi[(size_t)BB * NH];
__device__ __align__(16) __nv_bfloat16 g_h_lo[(size_t)BB * NH];
__device__ __align__(16) __nv_bfloat16 g_w1h_hi[(size_t)NH * NI];
__device__ __align__(16) __nv_bfloat16 g_w1h_lo[(size_t)NH * NI];
__device__ __align__(16) __nv_bfloat16 g_w2h_hi[(size_t)NH * NH];
__device__ __align__(16) __nv_bfloat16 g_w2h_lo[(size_t)NH * NH];
__device__ __align__(16) __nv_bfloat16 g_w1o_hi[(size_t)NO * NI];
__device__ __align__(16) __nv_bfloat16 g_w1o_lo[(size_t)NO * NI];
__device__ __align__(16) __nv_bfloat16 g_w2o_hi[(size_t)NO * NH];
__device__ __align__(16) __nv_bfloat16 g_w2o_lo[(size_t)NO * NH];

// ---------------------------------------------------------------------------
// PTX helpers (portable ISA only: cp.async, ldmatrix, mma.sync)
// ---------------------------------------------------------------------------
__device__ __forceinline__ uint32_t smem_u32(const void* p) {
    uint32_t a;
    asm("{ .reg .u64 t; cvta.to.shared.u64 t, %1; cvt.u32.u64 %0, t; }"
        : "=r"(a) : "l"(p));
    return a;
}

__device__ __forceinline__ void cp16(uint32_t dst, const void* src) {
    asm volatile("cp.async.cg.shared.global [%0], [%1], 16;\n"
                 :: "r"(dst), "l"(src));
}
__device__ __forceinline__ void cp_commit() {
    asm volatile("cp.async.commit_group;\n" ::: "memory");
}
template <int N> __device__ __forceinline__ void cp_wait() {
    asm volatile("cp.async.wait_group %0;\n" :: "n"(N) : "memory");
}

__device__ __forceinline__ void ldmx4(uint32_t* r, uint32_t addr) {
    asm volatile("ldmatrix.sync.aligned.m8n8.x4.shared.b16 {%0,%1,%2,%3}, [%4];"
                 : "=r"(r[0]), "=r"(r[1]), "=r"(r[2]), "=r"(r[3]) : "r"(addr));
}

__device__ __forceinline__ void mma16816(float* c, const uint32_t* a, const uint32_t* b) {
    asm volatile(
        "mma.sync.aligned.m16n8k16.row.col.f32.bf16.bf16.f32 "
        "{%0,%1,%2,%3}, {%4,%5,%6,%7}, {%8,%9}, {%0,%1,%2,%3};"
        : "+f"(c[0]), "+f"(c[1]), "+f"(c[2]), "+f"(c[3])
        : "r"(a[0]), "r"(a[1]), "r"(a[2]), "r"(a[3]), "r"(b[0]), "r"(b[1]));
}

// ---------------------------------------------------------------------------
// fp32 -> (bf16 hi, bf16 lo) split
// ---------------------------------------------------------------------------
__global__ __launch_bounds__(256) void split_bf16(
    const float4* __restrict__ x, uint2* __restrict__ hi, uint2* __restrict__ lo, int n4)
{
    int i = blockIdx.x * 256 + threadIdx.x;
    if (i >= n4) return;
    float4 v = x[i];
    __nv_bfloat16 h0 = __float2bfloat16_rn(v.x);
    __nv_bfloat16 h1 = __float2bfloat16_rn(v.y);
    __nv_bfloat16 h2 = __float2bfloat16_rn(v.z);
    __nv_bfloat16 h3 = __float2bfloat16_rn(v.w);
    __nv_bfloat16 l0 = __float2bfloat16_rn(v.x - __bfloat162float(h0));
    __nv_bfloat16 l1 = __float2bfloat16_rn(v.y - __bfloat162float(h1));
    __nv_bfloat16 l2 = __float2bfloat16_rn(v.z - __bfloat162float(h2));
    __nv_bfloat16 l3 = __float2bfloat16_rn(v.w - __bfloat162float(h3));
    uint2 H, L;
    H.x = (uint32_t)__bfloat16_as_ushort(h0) | ((uint32_t)__bfloat16_as_ushort(h1) << 16);
    H.y = (uint32_t)__bfloat16_as_ushort(h2) | ((uint32_t)__bfloat16_as_ushort(h3) << 16);
    L.x = (uint32_t)__bfloat16_as_ushort(l0) | ((uint32_t)__bfloat16_as_ushort(l1) << 16);
    L.y = (uint32_t)__bfloat16_as_ushort(l2) | ((uint32_t)__bfloat16_as_ushort(l3) << 16);
    hi[i] = H;
    lo[i] = L;
}

// ---------------------------------------------------------------------------
// mma.sync GEMM: out = relu( A1@W1^T + A2@W2^T + bias1 + bias2 )
// split-bf16 emulation: hi*hi + hi*lo + lo*hi, fp32 register accumulators.
// CTA tile 128x128, BK=32, 256 threads (8 warps = 2m x 4n, warp tile 64x32).
// Smem rows padded to 80B (16B pad) -> ldmatrix phase conflict-free.
// 3-stage cp.async pipeline.
// ---------------------------------------------------------------------------
__global__ __launch_bounds__(256, 1) void gemm_mma(
    const __nv_bfloat16* __restrict__ A1h, const __nv_bfloat16* __restrict__ A1l,
    const __nv_bfloat16* __restrict__ A2h, const __nv_bfloat16* __restrict__ A2l,
    const __nv_bfloat16* __restrict__ B1h, const __nv_bfloat16* __restrict__ B1l,
    const __nv_bfloat16* __restrict__ B2h, const __nv_bfloat16* __restrict__ B2l,
    const float* __restrict__ bias1, const float* __restrict__ bias2,
    float* __restrict__ out, int N, int K1, int K2)
{
    constexpr int ROWB  = 80;            // smem bytes per 32-bf16 row (64 + 16 pad)
    constexpr int TILE  = 128 * ROWB;    // one matrix tile (A or W, hi or lo)
    constexpr int STAGE = 4 * TILE;      // Ahi, Alo, Whi, Wlo

    extern __shared__ char smraw[];
    const uint32_t sb = smem_u32(smraw);

    const int t = threadIdx.x, wid = t >> 5, lane = t & 31;
    const int m0 = blockIdx.y * 128, n0 = blockIdx.x * 128;
    const int wm = wid >> 2, wn = wid & 3;   // warp tile: rows wm*64, cols wn*32

    // ldmatrix per-lane byte offsets within a tile
    // A (16x16 block): rows 0-15 from lanes (lane&15), k-half from lane>>4
    const uint32_t aOff = (uint32_t)((wm * 64 + (lane & 15)) * ROWB + (lane >> 4) * 16);
    // W (two n8 tiles per x4): n-row = (lane>>4)*8 + (lane&7), k-half = (lane>>3)&1
    const uint32_t bOff = (uint32_t)((wn * 32 + ((lane >> 4) << 3) + (lane & 7)) * ROWB
                                     + ((lane >> 3) & 1) * 16);

    float acc[4][4][4];
#pragma unroll
    for (int i = 0; i < 4; ++i)
#pragma unroll
        for (int j = 0; j < 4; ++j)
#pragma unroll
            for (int k = 0; k < 4; ++k) acc[i][j][k] = 0.f;

    const int NC = (K1 + K2) / 32;

    auto load_chunk = [&](int c, int s) {
        const int k0 = c * 32;
        const __nv_bfloat16 *Ah, *Al, *Wh, *Wl;
        int lda, ko;
        if (k0 < K1) { Ah = A1h; Al = A1l; Wh = B1h; Wl = B1l; lda = K1; ko = k0; }
        else         { Ah = A2h; Al = A2l; Wh = B2h; Wl = B2l; lda = K2; ko = k0 - K1; }
        const uint32_t st = sb + (uint32_t)s * STAGE;
#pragma unroll
        for (int q = 0; q < 2; ++q) {
            int idx = q * 256 + t;
            int row = idx >> 2, ch = idx & 3;       // 128 rows x 4 x 16B
            uint32_t d = st + (uint32_t)(row * ROWB + ch * 16);
            size_t offA = (size_t)(m0 + row) * lda + ko + ch * 8;
            size_t offB = (size_t)(n0 + row) * lda + ko + ch * 8;
            cp16(d,            Ah + offA);
            cp16(d + TILE,     Al + offA);
            cp16(d + 2 * TILE, Wh + offB);
            cp16(d + 3 * TILE, Wl + offB);
        }
    };

    // Prologue: fill 3 stages
    load_chunk(0, 0); cp_commit();
    load_chunk(1, 1); cp_commit();
    load_chunk(2, 2); cp_commit();

    int s = 0;
    for (int c = 0; c < NC; ++c) {
        cp_wait<2>();
        __syncthreads();

        const uint32_t st = sb + (uint32_t)s * STAGE;
#pragma unroll
        for (int kk = 0; kk < 2; ++kk) {
            uint32_t ah[4][4], al[4][4];
#pragma unroll
            for (int mt = 0; mt < 4; ++mt) {
                uint32_t a = st + aOff + (uint32_t)(mt * 16 * ROWB + kk * 32);
                ldmx4(ah[mt], a);
                ldmx4(al[mt], a + TILE);
            }
            uint32_t bh[2][4], bl[2][4];
#pragma unroll
            for (int p = 0; p < 2; ++p) {
                uint32_t b = st + 2 * TILE + bOff + (uint32_t)(p * 16 * ROWB + kk * 32);
                ldmx4(bh[p], b);
                ldmx4(bl[p], b + TILE);
            }
#pragma unroll
            for (int mt = 0; mt < 4; ++mt) {
#pragma unroll
                for (int nt = 0; nt < 4; ++nt) {
                    const uint32_t* BH = &bh[nt >> 1][(nt & 1) * 2];
                    const uint32_t* BL = &bl[nt >> 1][(nt & 1) * 2];
                    mma16816(acc[mt][nt], ah[mt], BH);
                    mma16816(acc[mt][nt], ah[mt], BL);
                    mma16816(acc[mt][nt], al[mt], BH);
                }
            }
        }

        __syncthreads();
        if (c + 3 < NC) load_chunk(c + 3, s);
        cp_commit();                     // empty groups at tail keep counts aligned
        s = (s == 2) ? 0 : s + 1;
    }

    // Epilogue: bias + ReLU, write float2 per fragment row
    const int g = lane >> 2, q2 = (lane & 3) * 2;
#pragma unroll
    for (int nt = 0; nt < 4; ++nt) {
        int col = n0 + wn * 32 + nt * 8 + q2;
        float b0 = bias1[col] + bias2[col];
        float b1 = bias1[col + 1] + bias2[col + 1];
#pragma unroll
        for (int mt = 0; mt < 4; ++mt) {
            int r0 = m0 + wm * 64 + mt * 16 + g;
            float2 v0, v1;
            v0.x = fmaxf(acc[mt][nt][0] + b0, 0.f);
            v0.y = fmaxf(acc[mt][nt][1] + b1, 0.f);
            v1.x = fmaxf(acc[mt][nt][2] + b0, 0.f);
            v1.y = fmaxf(acc[mt][nt][3] + b1, 0.f);
            *(float2*)&out[(size_t)r0 * N + col]       = v0;
            *(float2*)&out[(size_t)(r0 + 8) * N + col] = v1;
        }
    }
}

// ---------------------------------------------------------------------------
// Per-node LSTM pointwise step (unchanged — 22us total)
// ---------------------------------------------------------------------------
__global__ __launch_bounds__(256) void lstm_pointwise(
    const float* __restrict__ xin, const float* __restrict__ hprev,
    const float* __restrict__ cprev,
    const float* __restrict__ Wih, const float* __restrict__ Whh,
    const float* __restrict__ bias, const float* __restrict__ Whr,
    float* __restrict__ hnew, float* __restrict__ cnew,
    int N, int B)
{
    __shared__ float sX[32][33];
    __shared__ float sH[32][33];
    __shared__ float sHn[32][33];
    __shared__ float sWih[32][16];
    __shared__ float sWhh[32][16];
    __shared__ float sBias[32][16];
    __shared__ float sWhr[32][4];

    const int t = threadIdx.x;
    const int n0 = blockIdx.x * 32;
    const int b0 = blockIdx.y * 32;

    if (t < 128) {
        int nl = t >> 2, w = t & 3;
        ((float4*)&sWih[nl][0])[w]  = ((const float4*)Wih)[(size_t)(n0 + nl) * 4 + w];
        ((float4*)&sWhh[nl][0])[w]  = ((const float4*)Whh)[(size_t)(n0 + nl) * 4 + w];
        ((float4*)&sBias[nl][0])[w] = ((const float4*)bias)[(size_t)(n0 + nl) * 4 + w];
    }
    if (t < 32) {
        *(float4*)&sWhr[t][0] = ((const float4*)Whr)[(size_t)(n0 + t)];
    }

#pragma unroll
    for (int q = 0; q < 4; ++q) {
        int idx = t + 256 * q;
        int bl = idx >> 5, nl = idx & 31;
        sX[bl][nl] = xin  [(size_t)(b0 + bl) * N + n0 + nl];
        sH[bl][nl] = hprev[(size_t)(b0 + bl) * N + n0 + nl];
    }
    __syncthreads();

#pragma unroll
    for (int q = 0; q < 4; ++q) {
        int idx = t + 256 * q;
        int bl = idx & 31, nl = idx >> 5;
        int n = n0 + nl, b = b0 + bl;

        float x  = sX[bl][nl];
        float hp = sH[bl][nl];

        float g[16];
#pragma unroll
        for (int j = 0; j < 16; ++j)
            g[j] = fmaf(x, sWih[nl][j], fmaf(hp, sWhh[nl][j], sBias[nl][j]));

        float cp[4];
        *(float4*)cp = *(const float4*)&cprev[((size_t)n * B + b) * 4];

        float cn[4];
        float hsum = 0.f;
#pragma unroll
        for (int c = 0; c < 4; ++c) {
            float ig = 1.f / (1.f + expf(-g[c]));
            float fg = 1.f / (1.f + expf(-g[4 + c]));
            float gg = tanhf(g[8 + c]);
            float og = 1.f / (1.f + expf(-g[12 + c]));
            float cnc = fmaf(fg, cp[c], ig * gg);
            cn[c] = cnc;
            hsum = fmaf(og * tanhf(cnc), sWhr[nl][c], hsum);
        }
        *(float4*)&cnew[((size_t)n * B + b) * 4] =
            make_float4(cn[0], cn[1], cn[2], cn[3]);
        sHn[bl][nl] = hsum;
    }
    __syncthreads();

#pragma unroll
    for (int q = 0; q < 4; ++q) {
        int idx = t + 256 * q;
        int bl = idx >> 5, nl = idx & 31;
        hnew[(size_t)(b0 + bl) * N + n0 + nl] = sHn[bl][nl];
    }
}

// ---------------------------------------------------------------------------
// Launch
// ---------------------------------------------------------------------------
extern "C" void kernel_launch(void* const* d_in, const int* in_sizes, int n_in,
                              void* d_out, int out_size)
{
    const float* i_in    = (const float*)d_in[0];
    const float* h_in    = (const float*)d_in[1];
    const float* o_in    = (const float*)d_in[2];
    const float* h_cells = (const float*)d_in[3];
    const float* o_cells = (const float*)d_in[4];
    const float* W_i2h   = (const float*)d_in[5];
    const float* b_i2h   = (const float*)d_in[6];
    const float* W_h2h   = (const float*)d_in[7];
    const float* b_h2h   = (const float*)d_in[8];
    const float* W_i2o   = (const float*)d_in[9];
    const float* b_i2o   = (const float*)d_in[10];
    const float* W_h2o   = (const float*)d_in[11];
    const float* b_h2o   = (const float*)d_in[12];
    const float* Wih_h   = (const float*)d_in[13];
    const float* Whh_h   = (const float*)d_in[14];
    const float* bias_h  = (const float*)d_in[15];
    const float* Whr_h   = (const float*)d_in[16];
    const float* Wih_o   = (const float*)d_in[17];
    const float* Whh_o   = (const float*)d_in[18];
    const float* bias_o  = (const float*)d_in[19];
    const float* Whr_o   = (const float*)d_in[20];

    float* out    = (float*)d_out;
    float* new_h  = out;
    float* new_o  = new_h + (size_t)BB * NH;
    float* new_hc = new_o + (size_t)BB * NO;
    float* new_oc = new_hc + (size_t)NH * BB * CC;

    float* inh = nullptr; float* ino = nullptr;
    cudaGetSymbolAddress((void**)&inh, g_inh);
    cudaGetSymbolAddress((void**)&ino, g_ino);

    __nv_bfloat16 *ihi, *ilo, *hhi, *hlo;
    __nv_bfloat16 *w1hh, *w1hl, *w2hh, *w2hl, *w1oh, *w1ol, *w2oh, *w2ol;
    cudaGetSymbolAddress((void**)&ihi,  g_i_hi);
    cudaGetSymbolAddress((void**)&ilo,  g_i_lo);
    cudaGetSymbolAddress((void**)&hhi,  g_h_hi);
    cudaGetSymbolAddress((void**)&hlo,  g_h_lo);
    cudaGetSymbolAddress((void**)&w1hh, g_w1h_hi);
    cudaGetSymbolAddress((void**)&w1hl, g_w1h_lo);
    cudaGetSymbolAddress((void**)&w2hh, g_w2h_hi);
    cudaGetSymbolAddress((void**)&w2hl, g_w2h_lo);
    cudaGetSymbolAddress((void**)&w1oh, g_w1o_hi);
    cudaGetSymbolAddress((void**)&w1ol, g_w1o_lo);
    cudaGetSymbolAddress((void**)&w2oh, g_w2o_hi);
    cudaGetSymbolAddress((void**)&w2ol, g_w2o_lo);

    auto split = [&](const float* src, __nv_bfloat16* hi, __nv_bfloat16* lo, size_t n) {
        int n4 = (int)(n / 4);
        split_bf16<<<(n4 + 255) / 256, 256>>>(
            (const float4*)src, (uint2*)hi, (uint2*)lo, n4);
    };
    split(i_in,  ihi,  ilo,  (size_t)BB * NI);
    split(h_in,  hhi,  hlo,  (size_t)BB * NH);
    split(W_i2h, w1hh, w1hl, (size_t)NH * NI);
    split(W_h2h, w2hh, w2hl, (size_t)NH * NH);
    split(W_i2o, w1oh, w1ol, (size_t)NO * NI);
    split(W_h2o, w2oh, w2ol, (size_t)NO * NH);

    constexpr int SMEM = 3 * 4 * 128 * 80;   // 3 stages x 4 tiles x 10240B = 122880
    cudaFuncSetAttribute(gemm_mma, cudaFuncAttributeMaxDynamicSharedMemorySize, SMEM);

    gemm_mma<<<dim3(NH / 128, BB / 128), 256, SMEM>>>(
        ihi, ilo, hhi, hlo, w1hh, w1hl, w2hh, w2hl,
        b_i2h, b_h2h, inh, NH, NI, NH);
    gemm_mma<<<dim3(NO / 128, BB / 128), 256, SMEM>>>(
        ihi, ilo, hhi, hlo, w1oh, w1ol, w2oh, w2ol,
        b_i2o, b_h2o, ino, NO, NI, NH);

    lstm_pointwise<<<dim3(NH / 32, BB / 32), 256>>>(
        inh, h_in, h_cells, Wih_h, Whh_h, bias_h, Whr_h, new_h, new_hc, NH, BB);
    lstm_pointwise<<<dim3(NO / 32, BB / 32), 256>>>(
        ino, o_in, o_cells, Wih_o, Whh_o, bias_o, Whr_o, new_o, new_oc, NO, BB);
}

// round 6
// speedup vs baseline: 2.5289x; 1.0628x over previous
#include <cuda_runtime.h>
#include <cuda_bf16.h>
#include <cstdint>

// Problem constants
static constexpr int BB = 1024;   // batch
static constexpr int NI = 2048;
static constexpr int NH = 4096;
static constexpr int NO = 1024;
static constexpr int CC = 4;      // LSTM cell size

// ---------------------------------------------------------------------------
// Device scratch (no cudaMalloc allowed)
// ---------------------------------------------------------------------------
__device__ float g_inh[(size_t)BB * NH];
__device__ float g_ino[(size_t)BB * NO];

__device__ __align__(16) __nv_bfloat16 g_i_hi[(size_t)BB * NI];
__device__ __align__(16) __nv_bfloat16 g_i_lo[(size_t)BB * NI];
__device__ __align__(16) __nv_bfloat16 g_h_hi[(size_t)BB * NH];
__device__ __align__(16) __nv_bfloat16 g_h_lo[(size_t)BB * NH];
__device__ __align__(16) __nv_bfloat16 g_w1h_hi[(size_t)NH * NI];
__device__ __align__(16) __nv_bfloat16 g_w1h_lo[(size_t)NH * NI];
__device__ __align__(16) __nv_bfloat16 g_w2h_hi[(size_t)NH * NH];
__device__ __align__(16) __nv_bfloat16 g_w2h_lo[(size_t)NH * NH];
__device__ __align__(16) __nv_bfloat16 g_w1o_hi[(size_t)NO * NI];
__device__ __align__(16) __nv_bfloat16 g_w1o_lo[(size_t)NO * NI];
__device__ __align__(16) __nv_bfloat16 g_w2o_hi[(size_t)NO * NH];
__device__ __align__(16) __nv_bfloat16 g_w2o_lo[(size_t)NO * NH];

// ---------------------------------------------------------------------------
// PTX helpers (portable ISA only: cp.async, ldmatrix, mma.sync)
// ---------------------------------------------------------------------------
__device__ __forceinline__ uint32_t smem_u32(const void* p) {
    uint32_t a;
    asm("{ .reg .u64 t; cvta.to.shared.u64 t, %1; cvt.u32.u64 %0, t; }"
        : "=r"(a) : "l"(p));
    return a;
}

__device__ __forceinline__ void cp16(uint32_t dst, const void* src) {
    asm volatile("cp.async.cg.shared.global [%0], [%1], 16;\n"
                 :: "r"(dst), "l"(src));
}
__device__ __forceinline__ void cp_commit() {
    asm volatile("cp.async.commit_group;\n" ::: "memory");
}
template <int N> __device__ __forceinline__ void cp_wait() {
    asm volatile("cp.async.wait_group %0;\n" :: "n"(N) : "memory");
}

__device__ __forceinline__ void ldmx4(uint32_t* r, uint32_t addr) {
    asm volatile("ldmatrix.sync.aligned.m8n8.x4.shared.b16 {%0,%1,%2,%3}, [%4];"
                 : "=r"(r[0]), "=r"(r[1]), "=r"(r[2]), "=r"(r[3]) : "r"(addr));
}

__device__ __forceinline__ void mma16816(float* c, const uint32_t* a, const uint32_t* b) {
    asm volatile(
        "mma.sync.aligned.m16n8k16.row.col.f32.bf16.bf16.f32 "
        "{%0,%1,%2,%3}, {%4,%5,%6,%7}, {%8,%9}, {%0,%1,%2,%3};"
        : "+f"(c[0]), "+f"(c[1]), "+f"(c[2]), "+f"(c[3])
        : "r"(a[0]), "r"(a[1]), "r"(a[2]), "r"(a[3]), "r"(b[0]), "r"(b[1]));
}

// ---------------------------------------------------------------------------
// Fused fp32 -> (bf16 hi, bf16 lo) split over all 6 tensors (1 launch)
// ---------------------------------------------------------------------------
static constexpr size_t S0 = (size_t)BB * NI / 4;            // i
static constexpr size_t S1 = S0 + (size_t)BB * NH / 4;       // h
static constexpr size_t S2 = S1 + (size_t)NH * NI / 4;       // W_i2h
static constexpr size_t S3 = S2 + (size_t)NH * NH / 4;       // W_h2h
static constexpr size_t S4 = S3 + (size_t)NO * NI / 4;       // W_i2o
static constexpr size_t S5 = S4 + (size_t)NO * NH / 4;       // W_h2o

__global__ __launch_bounds__(256) void split_all(
    const float4* __restrict__ p0, const float4* __restrict__ p1,
    const float4* __restrict__ p2, const float4* __restrict__ p3,
    const float4* __restrict__ p4, const float4* __restrict__ p5,
    uint2* __restrict__ h0, uint2* __restrict__ l0,
    uint2* __restrict__ h1, uint2* __restrict__ l1,
    uint2* __restrict__ h2, uint2* __restrict__ l2,
    uint2* __restrict__ h3, uint2* __restrict__ l3,
    uint2* __restrict__ h4, uint2* __restrict__ l4,
    uint2* __restrict__ h5, uint2* __restrict__ l5)
{
    size_t i = (size_t)blockIdx.x * 256 + threadIdx.x;
    const float4* src; uint2 *hi, *lo; size_t base;
    if      (i < S0) { src = p0; hi = h0; lo = l0; base = 0;  }
    else if (i < S1) { src = p1; hi = h1; lo = l1; base = S0; }
    else if (i < S2) { src = p2; hi = h2; lo = l2; base = S1; }
    else if (i < S3) { src = p3; hi = h3; lo = l3; base = S2; }
    else if (i < S4) { src = p4; hi = h4; lo = l4; base = S3; }
    else             { src = p5; hi = h5; lo = l5; base = S4; }
    size_t j = i - base;
    float4 v = src[j];
    __nv_bfloat16 a0 = __float2bfloat16_rn(v.x);
    __nv_bfloat16 a1 = __float2bfloat16_rn(v.y);
    __nv_bfloat16 a2 = __float2bfloat16_rn(v.z);
    __nv_bfloat16 a3 = __float2bfloat16_rn(v.w);
    __nv_bfloat16 b0 = __float2bfloat16_rn(v.x - __bfloat162float(a0));
    __nv_bfloat16 b1 = __float2bfloat16_rn(v.y - __bfloat162float(a1));
    __nv_bfloat16 b2 = __float2bfloat16_rn(v.z - __bfloat162float(a2));
    __nv_bfloat16 b3 = __float2bfloat16_rn(v.w - __bfloat162float(a3));
    uint2 H, L;
    H.x = (uint32_t)__bfloat16_as_ushort(a0) | ((uint32_t)__bfloat16_as_ushort(a1) << 16);
    H.y = (uint32_t)__bfloat16_as_ushort(a2) | ((uint32_t)__bfloat16_as_ushort(a3) << 16);
    L.x = (uint32_t)__bfloat16_as_ushort(b0) | ((uint32_t)__bfloat16_as_ushort(b1) << 16);
    L.y = (uint32_t)__bfloat16_as_ushort(b2) | ((uint32_t)__bfloat16_as_ushort(b3) << 16);
    hi[j] = H;
    lo[j] = L;
}

// ---------------------------------------------------------------------------
// Combined mma.sync GEMM for BOTH aggregations in one launch.
//   tiles [0,256):  inh = relu(i@W_i2h^T + h@W_h2h^T + biases)   N=4096
//   tiles [256,320): ino = relu(i@W_i2o^T + h@W_h2o^T + biases)  N=1024
// split-bf16: hi*hi + hi*lo + lo*hi, fp32 register accumulators.
// CTA 128x128, BK=64, 512 threads (16 warps = 4m x 4n, warp tile 32x32),
// 2-stage cp.async pipeline. Smem rows 144B (128 + 16 pad), conflict-free.
// ---------------------------------------------------------------------------
__global__ __launch_bounds__(512, 1) void gemm_mma2(
    const __nv_bfloat16* __restrict__ iH, const __nv_bfloat16* __restrict__ iL,
    const __nv_bfloat16* __restrict__ hH, const __nv_bfloat16* __restrict__ hL,
    const __nv_bfloat16* __restrict__ w1hH, const __nv_bfloat16* __restrict__ w1hL,
    const __nv_bfloat16* __restrict__ w2hH, const __nv_bfloat16* __restrict__ w2hL,
    const __nv_bfloat16* __restrict__ w1oH, const __nv_bfloat16* __restrict__ w1oL,
    const __nv_bfloat16* __restrict__ w2oH, const __nv_bfloat16* __restrict__ w2oL,
    const float* __restrict__ b_i2h, const float* __restrict__ b_h2h,
    const float* __restrict__ b_i2o, const float* __restrict__ b_h2o,
    float* __restrict__ outh, float* __restrict__ outo)
{
    constexpr int ROWB  = 144;           // 64 bf16 = 128B + 16B pad
    constexpr int TILE  = 128 * ROWB;    // 18432 B
    constexpr int STAGE = 4 * TILE;      // Ahi, Alo, Whi, Wlo = 73728 B

    extern __shared__ char smraw[];
    const uint32_t sb = smem_u32(smraw);

    const int t = threadIdx.x, wid = t >> 5, lane = t & 31;
    const int wm = wid >> 2, wn = wid & 3;   // warp tile rows wm*32, cols wn*32

    // tile decode
    const int bid = blockIdx.x;
    const __nv_bfloat16 *W1h, *W1l, *W2h, *W2l;
    const float *bias1, *bias2;
    float* out;
    int m0, n0, N;
    if (bid < 256) {
        m0 = (bid >> 5) * 128; n0 = (bid & 31) * 128; N = NH;
        W1h = w1hH; W1l = w1hL; W2h = w2hH; W2l = w2hL;
        bias1 = b_i2h; bias2 = b_h2h; out = outh;
    } else {
        int r = bid - 256;
        m0 = (r >> 3) * 128; n0 = (r & 7) * 128; N = NO;
        W1h = w1oH; W1l = w1oL; W2h = w2oH; W2l = w2oL;
        bias1 = b_i2o; bias2 = b_h2o; out = outo;
    }

    // ldmatrix per-lane byte offsets within a tile
    const uint32_t aOff = (uint32_t)((wm * 32 + (lane & 15)) * ROWB + (lane >> 4) * 16);
    const uint32_t bOff = (uint32_t)((wn * 32 + ((lane >> 4) << 3) + (lane & 7)) * ROWB
                                     + ((lane >> 3) & 1) * 16);

    float acc[2][4][4];
#pragma unroll
    for (int i = 0; i < 2; ++i)
#pragma unroll
        for (int j = 0; j < 4; ++j)
#pragma unroll
            for (int k = 0; k < 4; ++k) acc[i][j][k] = 0.f;

    constexpr int NC = (NI + NH) / 64;   // 96 chunks of K=64

    auto load_chunk = [&](int c, int s) {
        const int k0 = c * 64;
        const __nv_bfloat16 *Ah, *Al, *Wh, *Wl;
        int lda, ko;
        if (k0 < NI) { Ah = iH; Al = iL; Wh = W1h; Wl = W1l; lda = NI; ko = k0; }
        else         { Ah = hH; Al = hL; Wh = W2h; Wl = W2l; lda = NH; ko = k0 - NI; }
        const uint32_t st = sb + (uint32_t)s * STAGE;
#pragma unroll
        for (int q = 0; q < 2; ++q) {
            int idx = q * 512 + t;
            int row = idx >> 3, ch = idx & 7;       // 128 rows x 8 x 16B
            uint32_t d = st + (uint32_t)(row * ROWB + ch * 16);
            size_t offA = (size_t)(m0 + row) * lda + ko + ch * 8;
            size_t offB = (size_t)(n0 + row) * lda + ko + ch * 8;
            cp16(d,            Ah + offA);
            cp16(d + TILE,     Al + offA);
            cp16(d + 2 * TILE, Wh + offB);
            cp16(d + 3 * TILE, Wl + offB);
        }
    };

    // Prologue: fill 2 stages
    load_chunk(0, 0); cp_commit();
    load_chunk(1, 1); cp_commit();

    int s = 0;
    for (int c = 0; c < NC; ++c) {
        cp_wait<1>();
        __syncthreads();

        const uint32_t st = sb + (uint32_t)s * STAGE;
#pragma unroll
        for (int kk = 0; kk < 4; ++kk) {
            uint32_t ah[2][4], al[2][4];
#pragma unroll
            for (int mt = 0; mt < 2; ++mt) {
                uint32_t a = st + aOff + (uint32_t)(mt * 16 * ROWB + kk * 32);
                ldmx4(ah[mt], a);
                ldmx4(al[mt], a + TILE);
            }
            uint32_t bh[2][4], bl[2][4];
#pragma unroll
            for (int p = 0; p < 2; ++p) {
                uint32_t b = st + 2 * TILE + bOff + (uint32_t)(p * 16 * ROWB + kk * 32);
                ldmx4(bh[p], b);
                ldmx4(bl[p], b + TILE);
            }
#pragma unroll
            for (int mt = 0; mt < 2; ++mt) {
#pragma unroll
                for (int nt = 0; nt < 4; ++nt) {
                    const uint32_t* BH = &bh[nt >> 1][(nt & 1) * 2];
                    const uint32_t* BL = &bl[nt >> 1][(nt & 1) * 2];
                    mma16816(acc[mt][nt], ah[mt], BH);
                    mma16816(acc[mt][nt], ah[mt], BL);
                    mma16816(acc[mt][nt], al[mt], BH);
                }
            }
        }

        __syncthreads();
        if (c + 2 < NC) load_chunk(c + 2, s);
        cp_commit();                     // empty groups at tail keep counts aligned
        s ^= 1;
    }

    // Epilogue: bias + ReLU, write float2 per fragment row
    const int g = lane >> 2, q2 = (lane & 3) * 2;
#pragma unroll
    for (int nt = 0; nt < 4; ++nt) {
        int col = n0 + wn * 32 + nt * 8 + q2;
        float b0 = bias1[col] + bias2[col];
        float b1 = bias1[col + 1] + bias2[col + 1];
#pragma unroll
        for (int mt = 0; mt < 2; ++mt) {
            int r0 = m0 + wm * 32 + mt * 16 + g;
            float2 v0, v1;
            v0.x = fmaxf(acc[mt][nt][0] + b0, 0.f);
            v0.y = fmaxf(acc[mt][nt][1] + b1, 0.f);
            v1.x = fmaxf(acc[mt][nt][2] + b0, 0.f);
            v1.y = fmaxf(acc[mt][nt][3] + b1, 0.f);
            *(float2*)&out[(size_t)r0 * N + col]       = v0;
            *(float2*)&out[(size_t)(r0 + 8) * N + col] = v1;
        }
    }
}

// ---------------------------------------------------------------------------
// Per-node LSTM pointwise step
// ---------------------------------------------------------------------------
__global__ __launch_bounds__(256) void lstm_pointwise(
    const float* __restrict__ xin, const float* __restrict__ hprev,
    const float* __restrict__ cprev,
    const float* __restrict__ Wih, const float* __restrict__ Whh,
    const float* __restrict__ bias, const float* __restrict__ Whr,
    float* __restrict__ hnew, float* __restrict__ cnew,
    int N, int B)
{
    __shared__ float sX[32][33];
    __shared__ float sH[32][33];
    __shared__ float sHn[32][33];
    __shared__ float sWih[32][16];
    __shared__ float sWhh[32][16];
    __shared__ float sBias[32][16];
    __shared__ float sWhr[32][4];

    const int t = threadIdx.x;
    const int n0 = blockIdx.x * 32;
    const int b0 = blockIdx.y * 32;

    if (t < 128) {
        int nl = t >> 2, w = t & 3;
        ((float4*)&sWih[nl][0])[w]  = ((const float4*)Wih)[(size_t)(n0 + nl) * 4 + w];
        ((float4*)&sWhh[nl][0])[w]  = ((const float4*)Whh)[(size_t)(n0 + nl) * 4 + w];
        ((float4*)&sBias[nl][0])[w] = ((const float4*)bias)[(size_t)(n0 + nl) * 4 + w];
    }
    if (t < 32) {
        *(float4*)&sWhr[t][0] = ((const float4*)Whr)[(size_t)(n0 + t)];
    }

#pragma unroll
    for (int q = 0; q < 4; ++q) {
        int idx = t + 256 * q;
        int bl = idx >> 5, nl = idx & 31;
        sX[bl][nl] = xin  [(size_t)(b0 + bl) * N + n0 + nl];
        sH[bl][nl] = hprev[(size_t)(b0 + bl) * N + n0 + nl];
    }
    __syncthreads();

#pragma unroll
    for (int q = 0; q < 4; ++q) {
        int idx = t + 256 * q;
        int bl = idx & 31, nl = idx >> 5;
        int n = n0 + nl, b = b0 + bl;

        float x  = sX[bl][nl];
        float hp = sH[bl][nl];

        float g[16];
#pragma unroll
        for (int j = 0; j < 16; ++j)
            g[j] = fmaf(x, sWih[nl][j], fmaf(hp, sWhh[nl][j], sBias[nl][j]));

        float cp[4];
        *(float4*)cp = *(const float4*)&cprev[((size_t)n * B + b) * 4];

        float cn[4];
        float hsum = 0.f;
#pragma unroll
        for (int c = 0; c < 4; ++c) {
            float ig = 1.f / (1.f + expf(-g[c]));
            float fg = 1.f / (1.f + expf(-g[4 + c]));
            float gg = tanhf(g[8 + c]);
            float og = 1.f / (1.f + expf(-g[12 + c]));
            float cnc = fmaf(fg, cp[c], ig * gg);
            cn[c] = cnc;
            hsum = fmaf(og * tanhf(cnc), sWhr[nl][c], hsum);
        }
        *(float4*)&cnew[((size_t)n * B + b) * 4] =
            make_float4(cn[0], cn[1], cn[2], cn[3]);
        sHn[bl][nl] = hsum;
    }
    __syncthreads();

#pragma unroll
    for (int q = 0; q < 4; ++q) {
        int idx = t + 256 * q;
        int bl = idx >> 5, nl = idx & 31;
        hnew[(size_t)(b0 + bl) * N + n0 + nl] = sHn[bl][nl];
    }
}

// ---------------------------------------------------------------------------
// Launch
// ---------------------------------------------------------------------------
extern "C" void kernel_launch(void* const* d_in, const int* in_sizes, int n_in,
                              void* d_out, int out_size)
{
    const float* i_in    = (const float*)d_in[0];
    const float* h_in    = (const float*)d_in[1];
    const float* o_in    = (const float*)d_in[2];
    const float* h_cells = (const float*)d_in[3];
    const float* o_cells = (const float*)d_in[4];
    const float* W_i2h   = (const float*)d_in[5];
    const float* b_i2h   = (const float*)d_in[6];
    const float* W_h2h   = (const float*)d_in[7];
    const float* b_h2h   = (const float*)d_in[8];
    const float* W_i2o   = (const float*)d_in[9];
    const float* b_i2o   = (const float*)d_in[10];
    const float* W_h2o   = (const float*)d_in[11];
    const float* b_h2o   = (const float*)d_in[12];
    const float* Wih_h   = (const float*)d_in[13];
    const float* Whh_h   = (const float*)d_in[14];
    const float* bias_h  = (const float*)d_in[15];
    const float* Whr_h   = (const float*)d_in[16];
    const float* Wih_o   = (const float*)d_in[17];
    const float* Whh_o   = (const float*)d_in[18];
    const float* bias_o  = (const float*)d_in[19];
    const float* Whr_o   = (const float*)d_in[20];

    float* out    = (float*)d_out;
    float* new_h  = out;
    float* new_o  = new_h + (size_t)BB * NH;
    float* new_hc = new_o + (size_t)BB * NO;
    float* new_oc = new_hc + (size_t)NH * BB * CC;

    float* inh = nullptr; float* ino = nullptr;
    cudaGetSymbolAddress((void**)&inh, g_inh);
    cudaGetSymbolAddress((void**)&ino, g_ino);

    __nv_bfloat16 *ihi, *ilo, *hhi, *hlo;
    __nv_bfloat16 *w1hh, *w1hl, *w2hh, *w2hl, *w1oh, *w1ol, *w2oh, *w2ol;
    cudaGetSymbolAddress((void**)&ihi,  g_i_hi);
    cudaGetSymbolAddress((void**)&ilo,  g_i_lo);
    cudaGetSymbolAddress((void**)&hhi,  g_h_hi);
    cudaGetSymbolAddress((void**)&hlo,  g_h_lo);
    cudaGetSymbolAddress((void**)&w1hh, g_w1h_hi);
    cudaGetSymbolAddress((void**)&w1hl, g_w1h_lo);
    cudaGetSymbolAddress((void**)&w2hh, g_w2h_hi);
    cudaGetSymbolAddress((void**)&w2hl, g_w2h_lo);
    cudaGetSymbolAddress((void**)&w1oh, g_w1o_hi);
    cudaGetSymbolAddress((void**)&w1ol, g_w1o_lo);
    cudaGetSymbolAddress((void**)&w2oh, g_w2o_hi);
    cudaGetSymbolAddress((void**)&w2ol, g_w2o_lo);

    // Fused hi/lo split: one launch covering all 6 tensors
    split_all<<<(unsigned)(S5 / 256), 256>>>(
        (const float4*)i_in, (const float4*)h_in, (const float4*)W_i2h,
        (const float4*)W_h2h, (const float4*)W_i2o, (const float4*)W_h2o,
        (uint2*)ihi,  (uint2*)ilo,  (uint2*)hhi,  (uint2*)hlo,
        (uint2*)w1hh, (uint2*)w1hl, (uint2*)w2hh, (uint2*)w2hl,
        (uint2*)w1oh, (uint2*)w1ol, (uint2*)w2oh, (uint2*)w2ol);

    // Combined GEMM: 256 inh tiles + 64 ino tiles
    constexpr int SMEM = 2 * 4 * 128 * 144;   // 2 stages x 4 tiles x 18432B = 147456
    cudaFuncSetAttribute(gemm_mma2, cudaFuncAttributeMaxDynamicSharedMemorySize, SMEM);
    gemm_mma2<<<320, 512, SMEM>>>(
        ihi, ilo, hhi, hlo,
        w1hh, w1hl, w2hh, w2hl, w1oh, w1ol, w2oh, w2ol,
        b_i2h, b_h2h, b_i2o, b_h2o, inh, ino);

    lstm_pointwise<<<dim3(NH / 32, BB / 32), 256>>>(
        inh, h_in, h_cells, Wih_h, Whh_h, bias_h, Whr_h, new_h, new_hc, NH, BB);
    lstm_pointwise<<<dim3(NO / 32, BB / 32), 256>>>(
        ino, o_in, o_cells, Wih_o, Whh_o, bias_o, Whr_o, new_o, new_oc, NO, BB);
}

// round 7
// speedup vs baseline: 3.9335x; 1.5554x over previous
#include <cuda_runtime.h>
#include <cuda_fp16.h>
#include <cstdint>

// Problem constants
static constexpr int BB = 1024;   // batch
static constexpr int NI = 2048;
static constexpr int NH = 4096;
static constexpr int NO = 1024;
static constexpr int CC = 4;      // LSTM cell size
static constexpr int KTOT = NI + NH;     // 6144
static constexpr int KHALF = KTOT / 2;   // 3072

// ---------------------------------------------------------------------------
// Device scratch (no cudaMalloc allowed)
// ---------------------------------------------------------------------------
__device__ float g_inh[2 * (size_t)BB * NH];   // split-K partials
__device__ float g_ino[2 * (size_t)BB * NO];

__device__ __align__(16) __half g_i_hi[(size_t)BB * NI];
__device__ __align__(16) __half g_i_lo[(size_t)BB * NI];
__device__ __align__(16) __half g_h_hi[(size_t)BB * NH];
__device__ __align__(16) __half g_h_lo[(size_t)BB * NH];
__device__ __align__(16) __half g_w1h_hi[(size_t)NH * NI];
__device__ __align__(16) __half g_w2h_hi[(size_t)NH * NH];
__device__ __align__(16) __half g_w1o_hi[(size_t)NO * NI];
__device__ __align__(16) __half g_w2o_hi[(size_t)NO * NH];

// ---------------------------------------------------------------------------
// PTX helpers (portable ISA only: cp.async, ldmatrix, mma.sync)
// ---------------------------------------------------------------------------
__device__ __forceinline__ uint32_t smem_u32(const void* p) {
    uint32_t a;
    asm("{ .reg .u64 t; cvta.to.shared.u64 t, %1; cvt.u32.u64 %0, t; }"
        : "=r"(a) : "l"(p));
    return a;
}

__device__ __forceinline__ void cp16(uint32_t dst, const void* src) {
    asm volatile("cp.async.cg.shared.global [%0], [%1], 16;\n"
                 :: "r"(dst), "l"(src));
}
__device__ __forceinline__ void cp_commit() {
    asm volatile("cp.async.commit_group;\n" ::: "memory");
}
template <int N> __device__ __forceinline__ void cp_wait() {
    asm volatile("cp.async.wait_group %0;\n" :: "n"(N) : "memory");
}

__device__ __forceinline__ void ldmx4(uint32_t* r, uint32_t addr) {
    asm volatile("ldmatrix.sync.aligned.m8n8.x4.shared.b16 {%0,%1,%2,%3}, [%4];"
                 : "=r"(r[0]), "=r"(r[1]), "=r"(r[2]), "=r"(r[3]) : "r"(addr));
}

__device__ __forceinline__ void mma16816(float* c, const uint32_t* a, const uint32_t* b) {
    asm volatile(
        "mma.sync.aligned.m16n8k16.row.col.f32.f16.f16.f32 "
        "{%0,%1,%2,%3}, {%4,%5,%6,%7}, {%8,%9}, {%0,%1,%2,%3};"
        : "+f"(c[0]), "+f"(c[1]), "+f"(c[2]), "+f"(c[3])
        : "r"(a[0]), "r"(a[1]), "r"(a[2]), "r"(a[3]), "r"(b[0]), "r"(b[1]));
}

// ---------------------------------------------------------------------------
// Fused fp32 -> fp16 split. Activations (i, h): hi + lo. Weights: hi only.
// ---------------------------------------------------------------------------
static constexpr size_t S0 = (size_t)BB * NI / 4;            // i
static constexpr size_t S1 = S0 + (size_t)BB * NH / 4;       // h
static constexpr size_t S2 = S1 + (size_t)NH * NI / 4;       // W_i2h
static constexpr size_t S3 = S2 + (size_t)NH * NH / 4;       // W_h2h
static constexpr size_t S4 = S3 + (size_t)NO * NI / 4;       // W_i2o
static constexpr size_t S5 = S4 + (size_t)NO * NH / 4;       // W_h2o

__global__ __launch_bounds__(256) void split_all(
    const float4* __restrict__ p0, const float4* __restrict__ p1,
    const float4* __restrict__ p2, const float4* __restrict__ p3,
    const float4* __restrict__ p4, const float4* __restrict__ p5,
    uint2* __restrict__ h0, uint2* __restrict__ l0,
    uint2* __restrict__ h1, uint2* __restrict__ l1,
    uint2* __restrict__ h2, uint2* __restrict__ h3,
    uint2* __restrict__ h4, uint2* __restrict__ h5)
{
    size_t i = (size_t)blockIdx.x * 256 + threadIdx.x;
    const float4* src; uint2 *hi, *lo; size_t base;
    if      (i < S0) { src = p0; hi = h0; lo = l0;      base = 0;  }
    else if (i < S1) { src = p1; hi = h1; lo = l1;      base = S0; }
    else if (i < S2) { src = p2; hi = h2; lo = nullptr; base = S1; }
    else if (i < S3) { src = p3; hi = h3; lo = nullptr; base = S2; }
    else if (i < S4) { src = p4; hi = h4; lo = nullptr; base = S3; }
    else             { src = p5; hi = h5; lo = nullptr; base = S4; }
    size_t j = i - base;
    float4 v = src[j];
    __half a0 = __float2half_rn(v.x);
    __half a1 = __float2half_rn(v.y);
    __half a2 = __float2half_rn(v.z);
    __half a3 = __float2half_rn(v.w);
    uint2 H;
    H.x = (uint32_t)__half_as_ushort(a0) | ((uint32_t)__half_as_ushort(a1) << 16);
    H.y = (uint32_t)__half_as_ushort(a2) | ((uint32_t)__half_as_ushort(a3) << 16);
    hi[j] = H;
    if (lo) {
        __half b0 = __float2half_rn(v.x - __half2float(a0));
        __half b1 = __float2half_rn(v.y - __half2float(a1));
        __half b2 = __float2half_rn(v.z - __half2float(a2));
        __half b3 = __float2half_rn(v.w - __half2float(a3));
        uint2 L;
        L.x = (uint32_t)__half_as_ushort(b0) | ((uint32_t)__half_as_ushort(b1) << 16);
        L.y = (uint32_t)__half_as_ushort(b2) | ((uint32_t)__half_as_ushort(b3) << 16);
        lo[j] = L;
    }
}

// ---------------------------------------------------------------------------
// Combined split-K2 mma.sync GEMM, both aggregations, one launch.
//   blockIdx.x in [0, 640): kh = bid & 1 (K half), tb = bid >> 1 (tile id)
//     tb [0,256):  inh tile -> partial outh[kh]   (N=4096)
//     tb [256,320): ino tile -> partial outo[kh]  (N=1024)
// fp16 2-product: (Ahi + Alo) @ Whi^T, fp32 register accumulators.
// NO bias/ReLU here: partials reduced (+bias+ReLU) in lstm_pointwise.
// CTA 128x128, BK=64, 512 threads (16 warps = 4m x 4n, warp tile 32x32),
// 2-stage cp.async pipeline. Smem rows 144B (128 + 16 pad), conflict-free.
// ---------------------------------------------------------------------------
__global__ __launch_bounds__(512, 1) void gemm_mma3(
    const __half* __restrict__ iH, const __half* __restrict__ iL,
    const __half* __restrict__ hH, const __half* __restrict__ hL,
    const __half* __restrict__ w1h, const __half* __restrict__ w2h,
    const __half* __restrict__ w1o, const __half* __restrict__ w2o,
    float* __restrict__ outh, float* __restrict__ outo)
{
    constexpr int ROWB  = 144;           // 64 fp16 = 128B + 16B pad
    constexpr int TILE  = 128 * ROWB;    // 18432 B
    constexpr int STAGE = 3 * TILE;      // Ahi, Alo, Whi = 55296 B

    extern __shared__ char smraw[];
    const uint32_t sb = smem_u32(smraw);

    const int t = threadIdx.x, wid = t >> 5, lane = t & 31;
    const int wm = wid >> 2, wn = wid & 3;

    const int bid = blockIdx.x;
    const int kh = bid & 1;
    const int tb = bid >> 1;
    const int kbase = kh * KHALF;

    const __half *W1, *W2;
    float* out;
    int m0, n0, N;
    if (tb < 256) {
        m0 = (tb >> 5) * 128; n0 = (tb & 31) * 128; N = NH;
        W1 = w1h; W2 = w2h;
        out = outh + (size_t)kh * BB * NH;
    } else {
        int r = tb - 256;
        m0 = (r >> 3) * 128; n0 = (r & 7) * 128; N = NO;
        W1 = w1o; W2 = w2o;
        out = outo + (size_t)kh * BB * NO;
    }

    // ldmatrix per-lane byte offsets within a tile
    const uint32_t aOff = (uint32_t)((wm * 32 + (lane & 15)) * ROWB + (lane >> 4) * 16);
    const uint32_t bOff = (uint32_t)((wn * 32 + ((lane >> 4) << 3) + (lane & 7)) * ROWB
                                     + ((lane >> 3) & 1) * 16);

    float acc[2][4][4];
#pragma unroll
    for (int i = 0; i < 2; ++i)
#pragma unroll
        for (int j = 0; j < 4; ++j)
#pragma unroll
            for (int k = 0; k < 4; ++k) acc[i][j][k] = 0.f;

    constexpr int NC = KHALF / 64;   // 48 chunks

    auto load_chunk = [&](int c, int s) {
        const int k0 = kbase + c * 64;
        const __half *Ah, *Al, *Wh;
        int lda, ko;
        if (k0 < NI) { Ah = iH; Al = iL; Wh = W1; lda = NI; ko = k0; }
        else         { Ah = hH; Al = hL; Wh = W2; lda = NH; ko = k0 - NI; }
        const uint32_t st = sb + (uint32_t)s * STAGE;
#pragma unroll
        for (int q = 0; q < 2; ++q) {
            int idx = q * 512 + t;
            int row = idx >> 3, ch = idx & 7;       // 128 rows x 8 x 16B
            uint32_t d = st + (uint32_t)(row * ROWB + ch * 16);
            size_t offA = (size_t)(m0 + row) * lda + ko + ch * 8;
            size_t offB = (size_t)(n0 + row) * lda + ko + ch * 8;
            cp16(d,            Ah + offA);
            cp16(d + TILE,     Al + offA);
            cp16(d + 2 * TILE, Wh + offB);
        }
    };

    // Prologue: fill 2 stages
    load_chunk(0, 0); cp_commit();
    load_chunk(1, 1); cp_commit();

    int s = 0;
    for (int c = 0; c < NC; ++c) {
        cp_wait<1>();
        __syncthreads();

        const uint32_t st = sb + (uint32_t)s * STAGE;
#pragma unroll
        for (int kk = 0; kk < 4; ++kk) {
            uint32_t ah[2][4], al[2][4];
#pragma unroll
            for (int mt = 0; mt < 2; ++mt) {
                uint32_t a = st + aOff + (uint32_t)(mt * 16 * ROWB + kk * 32);
                ldmx4(ah[mt], a);
                ldmx4(al[mt], a + TILE);
            }
            uint32_t bh[2][4];
#pragma unroll
            for (int p = 0; p < 2; ++p) {
                uint32_t b = st + 2 * TILE + bOff + (uint32_t)(p * 16 * ROWB + kk * 32);
                ldmx4(bh[p], b);
            }
#pragma unroll
            for (int mt = 0; mt < 2; ++mt) {
#pragma unroll
                for (int nt = 0; nt < 4; ++nt) {
                    const uint32_t* BH = &bh[nt >> 1][(nt & 1) * 2];
                    mma16816(acc[mt][nt], ah[mt], BH);
                    mma16816(acc[mt][nt], al[mt], BH);
                }
            }
        }

        __syncthreads();
        if (c + 2 < NC) load_chunk(c + 2, s);
        cp_commit();                     // empty groups at tail keep counts aligned
        s ^= 1;
    }

    // Epilogue: raw partial store (bias/ReLU applied at reduce in pointwise)
    const int g = lane >> 2, q2 = (lane & 3) * 2;
#pragma unroll
    for (int nt = 0; nt < 4; ++nt) {
        int col = n0 + wn * 32 + nt * 8 + q2;
#pragma unroll
        for (int mt = 0; mt < 2; ++mt) {
            int r0 = m0 + wm * 32 + mt * 16 + g;
            *(float2*)&out[(size_t)r0 * N + col] =
                make_float2(acc[mt][nt][0], acc[mt][nt][1]);
            *(float2*)&out[(size_t)(r0 + 8) * N + col] =
                make_float2(acc[mt][nt][2], acc[mt][nt][3]);
        }
    }
}

// ---------------------------------------------------------------------------
// Per-node LSTM pointwise step, fused with split-K reduce + agg bias + ReLU:
//   x = relu(xp0 + xp1 + ab1[n] + ab2[n])
// ---------------------------------------------------------------------------
__global__ __launch_bounds__(256) void lstm_pointwise(
    const float* __restrict__ xp0, const float* __restrict__ xp1,
    const float* __restrict__ ab1, const float* __restrict__ ab2,
    const float* __restrict__ hprev, const float* __restrict__ cprev,
    const float* __restrict__ Wih, const float* __restrict__ Whh,
    const float* __restrict__ bias, const float* __restrict__ Whr,
    float* __restrict__ hnew, float* __restrict__ cnew,
    int N, int B)
{
    __shared__ float sX[32][33];
    __shared__ float sH[32][33];
    __shared__ float sHn[32][33];
    __shared__ float sWih[32][16];
    __shared__ float sWhh[32][16];
    __shared__ float sBias[32][16];
    __shared__ float sWhr[32][4];
    __shared__ float sAggB[32];

    const int t = threadIdx.x;
    const int n0 = blockIdx.x * 32;
    const int b0 = blockIdx.y * 32;

    if (t < 128) {
        int nl = t >> 2, w = t & 3;
        ((float4*)&sWih[nl][0])[w]  = ((const float4*)Wih)[(size_t)(n0 + nl) * 4 + w];
        ((float4*)&sWhh[nl][0])[w]  = ((const float4*)Whh)[(size_t)(n0 + nl) * 4 + w];
        ((float4*)&sBias[nl][0])[w] = ((const float4*)bias)[(size_t)(n0 + nl) * 4 + w];
    }
    if (t < 32) {
        *(float4*)&sWhr[t][0] = ((const float4*)Whr)[(size_t)(n0 + t)];
        sAggB[t] = ab1[n0 + t] + ab2[n0 + t];
    }

#pragma unroll
    for (int q = 0; q < 4; ++q) {
        int idx = t + 256 * q;
        int bl = idx >> 5, nl = idx & 31;
        size_t gi = (size_t)(b0 + bl) * N + n0 + nl;
        sX[bl][nl] = xp0[gi] + xp1[gi];
        sH[bl][nl] = hprev[gi];
    }
    __syncthreads();

#pragma unroll
    for (int q = 0; q < 4; ++q) {
        int idx = t + 256 * q;
        int bl = idx & 31, nl = idx >> 5;
        int n = n0 + nl, b = b0 + bl;

        float x  = fmaxf(sX[bl][nl] + sAggB[nl], 0.f);   // reduce + bias + ReLU
        float hp = sH[bl][nl];

        float g[16];
#pragma unroll
        for (int j = 0; j < 16; ++j)
            g[j] = fmaf(x, sWih[nl][j], fmaf(hp, sWhh[nl][j], sBias[nl][j]));

        float cp[4];
        *(float4*)cp = *(const float4*)&cprev[((size_t)n * B + b) * 4];

        float cn[4];
        float hsum = 0.f;
#pragma unroll
        for (int c = 0; c < 4; ++c) {
            float ig = 1.f / (1.f + expf(-g[c]));
            float fg = 1.f / (1.f + expf(-g[4 + c]));
            float gg = tanhf(g[8 + c]);
            float og = 1.f / (1.f + expf(-g[12 + c]));
            float cnc = fmaf(fg, cp[c], ig * gg);
            cn[c] = cnc;
            hsum = fmaf(og * tanhf(cnc), sWhr[nl][c], hsum);
        }
        *(float4*)&cnew[((size_t)n * B + b) * 4] =
            make_float4(cn[0], cn[1], cn[2], cn[3]);
        sHn[bl][nl] = hsum;
    }
    __syncthreads();

#pragma unroll
    for (int q = 0; q < 4; ++q) {
        int idx = t + 256 * q;
        int bl = idx >> 5, nl = idx & 31;
        hnew[(size_t)(b0 + bl) * N + n0 + nl] = sHn[bl][nl];
    }
}

// ---------------------------------------------------------------------------
// Launch
// ---------------------------------------------------------------------------
extern "C" void kernel_launch(void* const* d_in, const int* in_sizes, int n_in,
                              void* d_out, int out_size)
{
    const float* i_in    = (const float*)d_in[0];
    const float* h_in    = (const float*)d_in[1];
    const float* o_in    = (const float*)d_in[2];
    const float* h_cells = (const float*)d_in[3];
    const float* o_cells = (const float*)d_in[4];
    const float* W_i2h   = (const float*)d_in[5];
    const float* b_i2h   = (const float*)d_in[6];
    const float* W_h2h   = (const float*)d_in[7];
    const float* b_h2h   = (const float*)d_in[8];
    const float* W_i2o   = (const float*)d_in[9];
    const float* b_i2o   = (const float*)d_in[10];
    const float* W_h2o   = (const float*)d_in[11];
    const float* b_h2o   = (const float*)d_in[12];
    const float* Wih_h   = (const float*)d_in[13];
    const float* Whh_h   = (const float*)d_in[14];
    const float* bias_h  = (const float*)d_in[15];
    const float* Whr_h   = (const float*)d_in[16];
    const float* Wih_o   = (const float*)d_in[17];
    const float* Whh_o   = (const float*)d_in[18];
    const float* bias_o  = (const float*)d_in[19];
    const float* Whr_o   = (const float*)d_in[20];

    float* out    = (float*)d_out;
    float* new_h  = out;
    float* new_o  = new_h + (size_t)BB * NH;
    float* new_hc = new_o + (size_t)BB * NO;
    float* new_oc = new_hc + (size_t)NH * BB * CC;

    float* inh = nullptr; float* ino = nullptr;
    cudaGetSymbolAddress((void**)&inh, g_inh);
    cudaGetSymbolAddress((void**)&ino, g_ino);

    __half *ihi, *ilo, *hhi, *hlo, *w1hh, *w2hh, *w1oh, *w2oh;
    cudaGetSymbolAddress((void**)&ihi,  g_i_hi);
    cudaGetSymbolAddress((void**)&ilo,  g_i_lo);
    cudaGetSymbolAddress((void**)&hhi,  g_h_hi);
    cudaGetSymbolAddress((void**)&hlo,  g_h_lo);
    cudaGetSymbolAddress((void**)&w1hh, g_w1h_hi);
    cudaGetSymbolAddress((void**)&w2hh, g_w2h_hi);
    cudaGetSymbolAddress((void**)&w1oh, g_w1o_hi);
    cudaGetSymbolAddress((void**)&w2oh, g_w2o_hi);

    // Fused fp16 split: one launch covering all 6 tensors
    split_all<<<(unsigned)(S5 / 256), 256>>>(
        (const float4*)i_in, (const float4*)h_in, (const float4*)W_i2h,
        (const float4*)W_h2h, (const float4*)W_i2o, (const float4*)W_h2o,
        (uint2*)ihi, (uint2*)ilo, (uint2*)hhi, (uint2*)hlo,
        (uint2*)w1hh, (uint2*)w2hh, (uint2*)w1oh, (uint2*)w2oh);

    // Combined split-K2 GEMM: 640 CTAs (2 K-halves x 320 tiles)
    constexpr int SMEM = 2 * 3 * 128 * 144;   // 2 stages x 3 tiles x 18432B = 110592
    cudaFuncSetAttribute(gemm_mma3, cudaFuncAttributeMaxDynamicSharedMemorySize, SMEM);
    gemm_mma3<<<640, 512, SMEM>>>(
        ihi, ilo, hhi, hlo, w1hh, w2hh, w1oh, w2oh, inh, ino);

    // Pointwise LSTM, fused with split-K reduce + agg-bias + ReLU
    lstm_pointwise<<<dim3(NH / 32, BB / 32), 256>>>(
        inh, inh + (size_t)BB * NH, b_i2h, b_h2h,
        h_in, h_cells, Wih_h, Whh_h, bias_h, Whr_h, new_h, new_hc, NH, BB);
    lstm_pointwise<<<dim3(NO / 32, BB / 32), 256>>>(
        ino, ino + (size_t)BB * NO, b_i2o, b_h2o,
        o_in, o_cells, Wih_o, Whh_o, bias_o, Whr_o, new_o, new_oc, NO, BB);
}

// round 9
// speedup vs baseline: 5.8069x; 1.4763x over previous
#include <cuda_runtime.h>
#include <cuda_fp16.h>
#include <cstdint>

// Problem constants
static constexpr int BB = 1024;   // batch
static constexpr int NI = 2048;
static constexpr int NH = 4096;
static constexpr int NO = 1024;
static constexpr int CC = 4;      // LSTM cell size
static constexpr int KTOT = NI + NH;     // 6144
static constexpr int KHALF = KTOT / 2;   // 3072

// ---------------------------------------------------------------------------
// Device scratch (no cudaMalloc allowed)
// ---------------------------------------------------------------------------
__device__ float g_inh[2 * (size_t)BB * NH];   // split-K partials
__device__ float g_ino[2 * (size_t)BB * NO];

__device__ __align__(16) __half g_i_f16[(size_t)BB * NI];
__device__ __align__(16) __half g_h_f16[(size_t)BB * NH];
__device__ __align__(16) __half g_w1h_f16[(size_t)NH * NI];
__device__ __align__(16) __half g_w2h_f16[(size_t)NH * NH];
__device__ __align__(16) __half g_w1o_f16[(size_t)NO * NI];
__device__ __align__(16) __half g_w2o_f16[(size_t)NO * NH];

// ---------------------------------------------------------------------------
// PTX helpers (portable ISA only: cp.async, ldmatrix, mma.sync)
// ---------------------------------------------------------------------------
__device__ __forceinline__ uint32_t smem_u32(const void* p) {
    uint32_t a;
    asm("{ .reg .u64 t; cvta.to.shared.u64 t, %1; cvt.u32.u64 %0, t; }"
        : "=r"(a) : "l"(p));
    return a;
}

__device__ __forceinline__ void cp16(uint32_t dst, const void* src) {
    asm volatile("cp.async.cg.shared.global [%0], [%1], 16;\n"
                 :: "r"(dst), "l"(src));
}
__device__ __forceinline__ void cp_commit() {
    asm volatile("cp.async.commit_group;\n" ::: "memory");
}
template <int N> __device__ __forceinline__ void cp_wait() {
    asm volatile("cp.async.wait_group %0;\n" :: "n"(N) : "memory");
}

__device__ __forceinline__ void ldmx4(uint32_t* r, uint32_t addr) {
    asm volatile("ldmatrix.sync.aligned.m8n8.x4.shared.b16 {%0,%1,%2,%3}, [%4];"
                 : "=r"(r[0]), "=r"(r[1]), "=r"(r[2]), "=r"(r[3]) : "r"(addr));
}

__device__ __forceinline__ void mma16816(float* c, const uint32_t* a, const uint32_t* b) {
    asm volatile(
        "mma.sync.aligned.m16n8k16.row.col.f32.f16.f16.f32 "
        "{%0,%1,%2,%3}, {%4,%5,%6,%7}, {%8,%9}, {%0,%1,%2,%3};"
        : "+f"(c[0]), "+f"(c[1]), "+f"(c[2]), "+f"(c[3])
        : "r"(a[0]), "r"(a[1]), "r"(a[2]), "r"(a[3]), "r"(b[0]), "r"(b[1]));
}

// Fast transcendentals (hardware MUFU-based, err ~1e-6 — far under budget)
__device__ __forceinline__ float fsig(float x) {
    return __fdividef(1.f, 1.f + __expf(-x));
}
__device__ __forceinline__ float ftanh(float x) {
    return fmaf(2.f, fsig(2.f * x), -1.f);
}

// ---------------------------------------------------------------------------
// Fused fp32 -> fp16 convert over all 6 tensors (1 launch)
// ---------------------------------------------------------------------------
static constexpr size_t S0 = (size_t)BB * NI / 4;            // i
static constexpr size_t S1 = S0 + (size_t)BB * NH / 4;       // h
static constexpr size_t S2 = S1 + (size_t)NH * NI / 4;       // W_i2h
static constexpr size_t S3 = S2 + (size_t)NH * NH / 4;       // W_h2h
static constexpr size_t S4 = S3 + (size_t)NO * NI / 4;       // W_i2o
static constexpr size_t S5 = S4 + (size_t)NO * NH / 4;       // W_h2o

__global__ __launch_bounds__(256) void cvt_all(
    const float4* __restrict__ p0, const float4* __restrict__ p1,
    const float4* __restrict__ p2, const float4* __restrict__ p3,
    const float4* __restrict__ p4, const float4* __restrict__ p5,
    uint2* __restrict__ h0, uint2* __restrict__ h1,
    uint2* __restrict__ h2, uint2* __restrict__ h3,
    uint2* __restrict__ h4, uint2* __restrict__ h5)
{
    size_t i = (size_t)blockIdx.x * 256 + threadIdx.x;
    const float4* src; uint2* hi; size_t base;
    if      (i < S0) { src = p0; hi = h0; base = 0;  }
    else if (i < S1) { src = p1; hi = h1; base = S0; }
    else if (i < S2) { src = p2; hi = h2; base = S1; }
    else if (i < S3) { src = p3; hi = h3; base = S2; }
    else if (i < S4) { src = p4; hi = h4; base = S3; }
    else             { src = p5; hi = h5; base = S4; }
    size_t j = i - base;
    float4 v = src[j];
    __half a0 = __float2half_rn(v.x);
    __half a1 = __float2half_rn(v.y);
    __half a2 = __float2half_rn(v.z);
    __half a3 = __float2half_rn(v.w);
    uint2 H;
    H.x = (uint32_t)__half_as_ushort(a0) | ((uint32_t)__half_as_ushort(a1) << 16);
    H.y = (uint32_t)__half_as_ushort(a2) | ((uint32_t)__half_as_ushort(a3) << 16);
    hi[j] = H;
}

// ---------------------------------------------------------------------------
// Combined split-K2 mma.sync GEMM (pure fp16, single product), one launch.
//   blockIdx.x in [0, 640): kh = bid & 1 (K half), tb = bid >> 1 (tile id)
//     tb [0,256):  inh tile -> partial outh[kh]   (N=4096)
//     tb [256,320): ino tile -> partial outo[kh]  (N=1024)
// NO bias/ReLU here: partials reduced (+bias+ReLU) in lstm_pointwise.
// CTA 128x128, BK=64, 512 threads (16 warps = 4m x 4n, warp tile 32x32),
// 3-stage cp.async pipeline. Smem rows 144B (128 + 16 pad), conflict-free.
// ---------------------------------------------------------------------------
__global__ __launch_bounds__(512, 1) void gemm_f16(
    const __half* __restrict__ iF, const __half* __restrict__ hF,
    const __half* __restrict__ w1h, const __half* __restrict__ w2h,
    const __half* __restrict__ w1o, const __half* __restrict__ w2o,
    float* __restrict__ outh, float* __restrict__ outo)
{
    constexpr int ROWB  = 144;           // 64 fp16 = 128B + 16B pad
    constexpr int TILE  = 128 * ROWB;    // 18432 B
    constexpr int STAGE = 2 * TILE;      // A, W = 36864 B

    extern __shared__ char smraw[];
    const uint32_t sb = smem_u32(smraw);

    const int t = threadIdx.x, wid = t >> 5, lane = t & 31;
    const int wm = wid >> 2, wn = wid & 3;

    const int bid = blockIdx.x;
    const int kh = bid & 1;
    const int tb = bid >> 1;
    const int kbase = kh * KHALF;

    const __half *W1, *W2;
    float* out;
    int m0, n0, N;
    if (tb < 256) {
        m0 = (tb >> 5) * 128; n0 = (tb & 31) * 128; N = NH;
        W1 = w1h; W2 = w2h;
        out = outh + (size_t)kh * BB * NH;
    } else {
        int r = tb - 256;
        m0 = (r >> 3) * 128; n0 = (r & 7) * 128; N = NO;
        W1 = w1o; W2 = w2o;
        out = outo + (size_t)kh * BB * NO;
    }

    // ldmatrix per-lane byte offsets within a tile
    const uint32_t aOff = (uint32_t)((wm * 32 + (lane & 15)) * ROWB + (lane >> 4) * 16);
    const uint32_t bOff = (uint32_t)((wn * 32 + ((lane >> 4) << 3) + (lane & 7)) * ROWB
                                     + ((lane >> 3) & 1) * 16);

    float acc[2][4][4];
#pragma unroll
    for (int i = 0; i < 2; ++i)
#pragma unroll
        for (int j = 0; j < 4; ++j)
#pragma unroll
            for (int k = 0; k < 4; ++k) acc[i][j][k] = 0.f;

    constexpr int NC = KHALF / 64;   // 48 chunks

    auto load_chunk = [&](int c, int s) {
        const int k0 = kbase + c * 64;
        const __half *Ap, *Wp;
        int lda, ko;
        if (k0 < NI) { Ap = iF; Wp = W1; lda = NI; ko = k0; }
        else         { Ap = hF; Wp = W2; lda = NH; ko = k0 - NI; }
        const uint32_t st = sb + (uint32_t)s * STAGE;
#pragma unroll
        for (int q = 0; q < 2; ++q) {
            int idx = q * 512 + t;
            int row = idx >> 3, ch = idx & 7;       // 128 rows x 8 x 16B
            uint32_t d = st + (uint32_t)(row * ROWB + ch * 16);
            cp16(d,        Ap + (size_t)(m0 + row) * lda + ko + ch * 8);
            cp16(d + TILE, Wp + (size_t)(n0 + row) * lda + ko + ch * 8);
        }
    };

    // Prologue: fill 3 stages
    load_chunk(0, 0); cp_commit();
    load_chunk(1, 1); cp_commit();
    load_chunk(2, 2); cp_commit();

    int s = 0;
    for (int c = 0; c < NC; ++c) {
        cp_wait<2>();
        __syncthreads();

        const uint32_t st = sb + (uint32_t)s * STAGE;
#pragma unroll
        for (int kk = 0; kk < 4; ++kk) {
            uint32_t ah[2][4];
#pragma unroll
            for (int mt = 0; mt < 2; ++mt)
                ldmx4(ah[mt], st + aOff + (uint32_t)(mt * 16 * ROWB + kk * 32));
            uint32_t bh[2][4];
#pragma unroll
            for (int p = 0; p < 2; ++p)
                ldmx4(bh[p], st + TILE + bOff + (uint32_t)(p * 16 * ROWB + kk * 32));
#pragma unroll
            for (int mt = 0; mt < 2; ++mt)
#pragma unroll
                for (int nt = 0; nt < 4; ++nt)
                    mma16816(acc[mt][nt], ah[mt], &bh[nt >> 1][(nt & 1) * 2]);
        }

        __syncthreads();
        if (c + 3 < NC) load_chunk(c + 3, s);
        cp_commit();                     // empty groups at tail keep counts aligned
        s = (s == 2) ? 0 : s + 1;
    }

    // Epilogue: raw partial store (bias/ReLU applied at reduce in pointwise)
    const int g = lane >> 2, q2 = (lane & 3) * 2;
#pragma unroll
    for (int nt = 0; nt < 4; ++nt) {
        int col = n0 + wn * 32 + nt * 8 + q2;
#pragma unroll
        for (int mt = 0; mt < 2; ++mt) {
            int r0 = m0 + wm * 32 + mt * 16 + g;
            *(float2*)&out[(size_t)r0 * N + col] =
                make_float2(acc[mt][nt][0], acc[mt][nt][1]);
            *(float2*)&out[(size_t)(r0 + 8) * N + col] =
                make_float2(acc[mt][nt][2], acc[mt][nt][3]);
        }
    }
}

// ---------------------------------------------------------------------------
// Fused per-node LSTM pointwise for BOTH nets in one launch, with
// split-K reduce + agg bias + ReLU:  x = relu(xp0 + xp1 + ab1[n] + ab2[n])
//   blockIdx.x [0,128): h-net (N=4096), [128,160): o-net (N=1024)
// ---------------------------------------------------------------------------
__global__ __launch_bounds__(256) void lstm_pointwise2(
    const float* __restrict__ xph, const float* __restrict__ b_i2h,
    const float* __restrict__ b_h2h,
    const float* __restrict__ h_in, const float* __restrict__ h_cells,
    const float* __restrict__ Wih_h, const float* __restrict__ Whh_h,
    const float* __restrict__ bias_h, const float* __restrict__ Whr_h,
    float* __restrict__ new_h, float* __restrict__ new_hc,
    const float* __restrict__ xpo, const float* __restrict__ b_i2o,
    const float* __restrict__ b_h2o,
    const float* __restrict__ o_in, const float* __restrict__ o_cells,
    const float* __restrict__ Wih_o, const float* __restrict__ Whh_o,
    const float* __restrict__ bias_o, const float* __restrict__ Whr_o,
    float* __restrict__ new_o, float* __restrict__ new_oc)
{
    __shared__ float sX[32][33];
    __shared__ float sH[32][33];
    __shared__ float sHn[32][33];
    __shared__ float sWih[32][16];
    __shared__ float sWhh[32][16];
    __shared__ float sBias[32][16];
    __shared__ float sWhr[32][4];
    __shared__ float sAggB[32];

    const int t = threadIdx.x;
    const int bx = blockIdx.x;
    const int b0 = blockIdx.y * 32;

    const float *xp0, *ab1, *ab2, *hprev, *cprev, *Wih, *Whh, *bias, *Whr;
    float *hnew, *cnew;
    int N, n0;
    if (bx < NH / 32) {
        N = NH; n0 = bx * 32;
        xp0 = xph; ab1 = b_i2h; ab2 = b_h2h; hprev = h_in; cprev = h_cells;
        Wih = Wih_h; Whh = Whh_h; bias = bias_h; Whr = Whr_h;
        hnew = new_h; cnew = new_hc;
    } else {
        N = NO; n0 = (bx - NH / 32) * 32;
        xp0 = xpo; ab1 = b_i2o; ab2 = b_h2o; hprev = o_in; cprev = o_cells;
        Wih = Wih_o; Whh = Whh_o; bias = bias_o; Whr = Whr_o;
        hnew = new_o; cnew = new_oc;
    }
    const float* xp1 = xp0 + (size_t)BB * N;   // second split-K partial
    const int B = BB;

    if (t < 128) {
        int nl = t >> 2, w = t & 3;
        ((float4*)&sWih[nl][0])[w]  = ((const float4*)Wih)[(size_t)(n0 + nl) * 4 + w];
        ((float4*)&sWhh[nl][0])[w]  = ((const float4*)Whh)[(size_t)(n0 + nl) * 4 + w];
        ((float4*)&sBias[nl][0])[w] = ((const float4*)bias)[(size_t)(n0 + nl) * 4 + w];
    }
    if (t < 32) {
        *(float4*)&sWhr[t][0] = ((const float4*)Whr)[(size_t)(n0 + t)];
        sAggB[t] = ab1[n0 + t] + ab2[n0 + t];
    }

#pragma unroll
    for (int q = 0; q < 4; ++q) {
        int idx = t + 256 * q;
        int bl = idx >> 5, nl = idx & 31;
        size_t gi = (size_t)(b0 + bl) * N + n0 + nl;
        sX[bl][nl] = xp0[gi] + xp1[gi];
        sH[bl][nl] = hprev[gi];
    }
    __syncthreads();

#pragma unroll
    for (int q = 0; q < 4; ++q) {
        int idx = t + 256 * q;
        int bl = idx & 31, nl = idx >> 5;
        int n = n0 + nl, b = b0 + bl;

        float x  = fmaxf(sX[bl][nl] + sAggB[nl], 0.f);   // reduce + bias + ReLU
        float hp = sH[bl][nl];

        float g[16];
#pragma unroll
        for (int j = 0; j < 16; ++j)
            g[j] = fmaf(x, sWih[nl][j], fmaf(hp, sWhh[nl][j], sBias[nl][j]));

        float cp[4];
        *(float4*)cp = *(const float4*)&cprev[((size_t)n * B + b) * 4];

        float cn[4];
        float hsum = 0.f;
#pragma unroll
        for (int c = 0; c < 4; ++c) {
            float ig = fsig(g[c]);
            float fg = fsig(g[4 + c]);
            float gg = ftanh(g[8 + c]);
            float og = fsig(g[12 + c]);
            float cnc = fmaf(fg, cp[c], ig * gg);
            cn[c] = cnc;
            hsum = fmaf(og * ftanh(cnc), sWhr[nl][c], hsum);
        }
        *(float4*)&cnew[((size_t)n * B + b) * 4] =
            make_float4(cn[0], cn[1], cn[2], cn[3]);
        sHn[bl][nl] = hsum;
    }
    __syncthreads();

#pragma unroll
    for (int q = 0; q < 4; ++q) {
        int idx = t + 256 * q;
        int bl = idx >> 5, nl = idx & 31;
        hnew[(size_t)(b0 + bl) * N + n0 + nl] = sHn[bl][nl];
    }
}

// ---------------------------------------------------------------------------
// Launch
// ---------------------------------------------------------------------------
extern "C" void kernel_launch(void* const* d_in, const int* in_sizes, int n_in,
                              void* d_out, int out_size)
{
    const float* i_in    = (const float*)d_in[0];
    const float* h_in    = (const float*)d_in[1];
    const float* o_in    = (const float*)d_in[2];
    const float* h_cells = (const float*)d_in[3];
    const float* o_cells = (const float*)d_in[4];
    const float* W_i2h   = (const float*)d_in[5];
    const float* b_i2h   = (const float*)d_in[6];
    const float* W_h2h   = (const float*)d_in[7];
    const float* b_h2h   = (const float*)d_in[8];
    const float* W_i2o   = (const float*)d_in[9];
    const float* b_i2o   = (const float*)d_in[10];
    const float* W_h2o   = (const float*)d_in[11];
    const float* b_h2o   = (const float*)d_in[12];
    const float* Wih_h   = (const float*)d_in[13];
    const float* Whh_h   = (const float*)d_in[14];
    const float* bias_h  = (const float*)d_in[15];
    const float* Whr_h   = (const float*)d_in[16];
    const float* Wih_o   = (const float*)d_in[17];
    const float* Whh_o   = (const float*)d_in[18];
    const float* bias_o  = (const float*)d_in[19];
    const float* Whr_o   = (const float*)d_in[20];

    float* out    = (float*)d_out;
    float* new_h  = out;
    float* new_o  = new_h + (size_t)BB * NH;
    float* new_hc = new_o + (size_t)BB * NO;
    float* new_oc = new_hc + (size_t)NH * BB * CC;

    float* inh = nullptr; float* ino = nullptr;
    cudaGetSymbolAddress((void**)&inh, g_inh);
    cudaGetSymbolAddress((void**)&ino, g_ino);

    __half *if16, *hf16, *w1hh, *w2hh, *w1oh, *w2oh;
    cudaGetSymbolAddress((void**)&if16, g_i_f16);
    cudaGetSymbolAddress((void**)&hf16, g_h_f16);
    cudaGetSymbolAddress((void**)&w1hh, g_w1h_f16);
    cudaGetSymbolAddress((void**)&w2hh, g_w2h_f16);
    cudaGetSymbolAddress((void**)&w1oh, g_w1o_f16);
    cudaGetSymbolAddress((void**)&w2oh, g_w2o_f16);

    // Fused fp16 convert: one launch covering all 6 tensors
    cvt_all<<<(unsigned)(S5 / 256), 256>>>(
        (const float4*)i_in, (const float4*)h_in, (const float4*)W_i2h,
        (const float4*)W_h2h, (const float4*)W_i2o, (const float4*)W_h2o,
        (uint2*)if16, (uint2*)hf16,
        (uint2*)w1hh, (uint2*)w2hh, (uint2*)w1oh, (uint2*)w2oh);

    // Combined split-K2 GEMM: 640 CTAs (2 K-halves x 320 tiles)
    constexpr int SMEM = 3 * 2 * 128 * 144;   // 3 stages x 2 tiles x 18432B = 110592
    cudaFuncSetAttribute(gemm_f16, cudaFuncAttributeMaxDynamicSharedMemorySize, SMEM);
    gemm_f16<<<640, 512, SMEM>>>(
        if16, hf16, w1hh, w2hh, w1oh, w2oh, inh, ino);

    // Fused pointwise for both nets (split-K reduce + agg-bias + ReLU + LSTM)
    lstm_pointwise2<<<dim3((NH + NO) / 32, BB / 32), 256>>>(
        inh, b_i2h, b_h2h, h_in, h_cells, Wih_h, Whh_h, bias_h, Whr_h,
        new_h, new_hc,
        ino, b_i2o, b_h2o, o_in, o_cells, Wih_o, Whh_o, bias_o, Whr_o,
        new_o, new_oc);
}

// round 12
// speedup vs baseline: 5.8447x; 1.0065x over previous
#include <cuda_runtime.h>
#include <cuda_fp16.h>
#include <cstdint>

// Problem constants
static constexpr int BB = 1024;   // batch
static constexpr int NI = 2048;
static constexpr int NH = 4096;
static constexpr int NO = 1024;
static constexpr int CC = 4;      // LSTM cell size
static constexpr int KTOT = NI + NH;     // 6144
static constexpr int KHALF = KTOT / 2;   // 3072

// ---------------------------------------------------------------------------
// Device scratch (no cudaMalloc allowed)
// ---------------------------------------------------------------------------
__device__ float g_inh[2 * (size_t)BB * NH];   // split-K partials
__device__ float g_ino[2 * (size_t)BB * NO];

__device__ __align__(16) __half g_i_f16[(size_t)BB * NI];
__device__ __align__(16) __half g_h_f16[(size_t)BB * NH];
__device__ __align__(16) __half g_w1h_f16[(size_t)NH * NI];
__device__ __align__(16) __half g_w2h_f16[(size_t)NH * NH];
__device__ __align__(16) __half g_w1o_f16[(size_t)NO * NI];
__device__ __align__(16) __half g_w2o_f16[(size_t)NO * NH];

// ---------------------------------------------------------------------------
// PTX helpers (portable ISA only: cp.async, ldmatrix, mma.sync)
// ---------------------------------------------------------------------------
__device__ __forceinline__ uint32_t smem_u32(const void* p) {
    uint32_t a;
    asm("{ .reg .u64 t; cvta.to.shared.u64 t, %1; cvt.u32.u64 %0, t; }"
        : "=r"(a) : "l"(p));
    return a;
}

__device__ __forceinline__ void cp16(uint32_t dst, const void* src) {
    asm volatile("cp.async.cg.shared.global [%0], [%1], 16;\n"
                 :: "r"(dst), "l"(src));
}
__device__ __forceinline__ void cp_commit() {
    asm volatile("cp.async.commit_group;\n" ::: "memory");
}
template <int N> __device__ __forceinline__ void cp_wait() {
    asm volatile("cp.async.wait_group %0;\n" :: "n"(N) : "memory");
}

__device__ __forceinline__ void ldmx4(uint32_t* r, uint32_t addr) {
    asm volatile("ldmatrix.sync.aligned.m8n8.x4.shared.b16 {%0,%1,%2,%3}, [%4];"
                 : "=r"(r[0]), "=r"(r[1]), "=r"(r[2]), "=r"(r[3]) : "r"(addr));
}

__device__ __forceinline__ void mma16816(float* c, const uint32_t* a, const uint32_t* b) {
    asm volatile(
        "mma.sync.aligned.m16n8k16.row.col.f32.f16.f16.f32 "
        "{%0,%1,%2,%3}, {%4,%5,%6,%7}, {%8,%9}, {%0,%1,%2,%3};"
        : "+f"(c[0]), "+f"(c[1]), "+f"(c[2]), "+f"(c[3])
        : "r"(a[0]), "r"(a[1]), "r"(a[2]), "r"(a[3]), "r"(b[0]), "r"(b[1]));
}

// Fast transcendentals (hardware MUFU-based, err ~1e-6 — far under budget)
__device__ __forceinline__ float fsig(float x) {
    return __fdividef(1.f, 1.f + __expf(-x));
}
__device__ __forceinline__ float ftanh(float x) {
    return fmaf(2.f, fsig(2.f * x), -1.f);
}

// ---------------------------------------------------------------------------
// Fused fp32 -> fp16 convert over all 6 tensors (1 launch, 2 float4/thread)
// ---------------------------------------------------------------------------
static constexpr size_t S0 = (size_t)BB * NI / 4;            // i
static constexpr size_t S1 = S0 + (size_t)BB * NH / 4;       // h
static constexpr size_t S2 = S1 + (size_t)NH * NI / 4;       // W_i2h
static constexpr size_t S3 = S2 + (size_t)NH * NH / 4;       // W_h2h
static constexpr size_t S4 = S3 + (size_t)NO * NI / 4;       // W_i2o
static constexpr size_t S5 = S4 + (size_t)NO * NH / 4;       // W_h2o

__global__ __launch_bounds__(256) void cvt_all(
    const float4* __restrict__ p0, const float4* __restrict__ p1,
    const float4* __restrict__ p2, const float4* __restrict__ p3,
    const float4* __restrict__ p4, const float4* __restrict__ p5,
    uint2* __restrict__ h0, uint2* __restrict__ h1,
    uint2* __restrict__ h2, uint2* __restrict__ h3,
    uint2* __restrict__ h4, uint2* __restrict__ h5)
{
#pragma unroll
    for (int rep = 0; rep < 2; ++rep) {
        size_t i = (size_t)blockIdx.x * 512 + rep * 256 + threadIdx.x;
        const float4* src; uint2* hi; size_t base;
        if      (i < S0) { src = p0; hi = h0; base = 0;  }
        else if (i < S1) { src = p1; hi = h1; base = S0; }
        else if (i < S2) { src = p2; hi = h2; base = S1; }
        else if (i < S3) { src = p3; hi = h3; base = S2; }
        else if (i < S4) { src = p4; hi = h4; base = S3; }
        else             { src = p5; hi = h5; base = S4; }
        size_t j = i - base;
        float4 v = src[j];
        __half a0 = __float2half_rn(v.x);
        __half a1 = __float2half_rn(v.y);
        __half a2 = __float2half_rn(v.z);
        __half a3 = __float2half_rn(v.w);
        uint2 H;
        H.x = (uint32_t)__half_as_ushort(a0) | ((uint32_t)__half_as_ushort(a1) << 16);
        H.y = (uint32_t)__half_as_ushort(a2) | ((uint32_t)__half_as_ushort(a3) << 16);
        hi[j] = H;
    }
}

// ---------------------------------------------------------------------------
// Combined split-K2 mma.sync GEMM (pure fp16), CTA tile 128x64, one launch.
//   blockIdx.x in [0, 1280): kh = bid & 1 (K half), tb = bid >> 1 (tile id)
//     tb [0,512):   inh tile: m0=(tb>>6)*128, n0=(tb&63)*64   (N=4096)
//     tb [512,640): ino tile: m0=(r>>4)*128,  n0=(r&15)*64    (N=1024)
// NO bias/ReLU here: partials reduced (+bias+ReLU) in lstm_pointwise.
// 512 threads = 16 warps (8m x 2n), warp tile 16x32, BK=64, 3-stage
// cp.async pipeline. 2 CTAs/SM co-resident (smem 82944B, <=64 regs).
// ---------------------------------------------------------------------------
__global__ __launch_bounds__(512, 2) void gemm_f16(
    const __half* __restrict__ iF, const __half* __restrict__ hF,
    const __half* __restrict__ w1h, const __half* __restrict__ w2h,
    const __half* __restrict__ w1o, const __half* __restrict__ w2o,
    float* __restrict__ outh, float* __restrict__ outo)
{
    constexpr int ROWB  = 144;             // 64 fp16 = 128B + 16B pad
    constexpr int ATILE = 128 * ROWB;      // 18432 B
    constexpr int WTILE = 64 * ROWB;       //  9216 B
    constexpr int STAGE = ATILE + WTILE;   // 27648 B

    extern __shared__ char smraw[];
    const uint32_t sb = smem_u32(smraw);

    const int t = threadIdx.x, wid = t >> 5, lane = t & 31;
    const int wm = wid >> 1, wn = wid & 1;   // 8m x 2n, warp tile 16x32

    const int bid = blockIdx.x;
    const int kh = bid & 1;
    const int tb = bid >> 1;
    const int kbase = kh * KHALF;

    const __half *W1, *W2;
    float* out;
    int m0, n0, N;
    if (tb < 512) {
        m0 = (tb >> 6) * 128; n0 = (tb & 63) * 64; N = NH;
        W1 = w1h; W2 = w2h;
        out = outh + (size_t)kh * BB * NH;
    } else {
        int r = tb - 512;
        m0 = (r >> 4) * 128; n0 = (r & 15) * 64; N = NO;
        W1 = w1o; W2 = w2o;
        out = outo + (size_t)kh * BB * NO;
    }

    // ldmatrix per-lane byte offsets within a tile
    const uint32_t aOff = (uint32_t)((wm * 16 + (lane & 15)) * ROWB + (lane >> 4) * 16);
    const uint32_t bOff = (uint32_t)((wn * 32 + ((lane >> 4) << 3) + (lane & 7)) * ROWB
                                     + ((lane >> 3) & 1) * 16);

    float acc[4][4];
#pragma unroll
    for (int j = 0; j < 4; ++j)
#pragma unroll
        for (int k = 0; k < 4; ++k) acc[j][k] = 0.f;

    constexpr int NC = KHALF / 64;   // 48 chunks

    auto load_chunk = [&](int c, int s) {
        const int k0 = kbase + c * 64;
        const __half *Ap, *Wp;
        int lda, ko;
        if (k0 < NI) { Ap = iF; Wp = W1; lda = NI; ko = k0; }
        else         { Ap = hF; Wp = W2; lda = NH; ko = k0 - NI; }
        const uint32_t st = sb + (uint32_t)s * STAGE;
        // A: 128 rows x 8 x 16B = 1024 transfers (2 per thread)
#pragma unroll
        for (int q = 0; q < 2; ++q) {
            int idx = q * 512 + t;
            int row = idx >> 3, ch = idx & 7;
            cp16(st + (uint32_t)(row * ROWB + ch * 16),
                 Ap + (size_t)(m0 + row) * lda + ko + ch * 8);
        }
        // W: 64 rows x 8 x 16B = 512 transfers (1 per thread)
        {
            int row = t >> 3, ch = t & 7;
            cp16(st + ATILE + (uint32_t)(row * ROWB + ch * 16),
                 Wp + (size_t)(n0 + row) * lda + ko + ch * 8);
        }
    };

    // Prologue: fill 3 stages
    load_chunk(0, 0); cp_commit();
    load_chunk(1, 1); cp_commit();
    load_chunk(2, 2); cp_commit();

    int s = 0;
    for (int c = 0; c < NC; ++c) {
        cp_wait<2>();
        __syncthreads();

        const uint32_t st = sb + (uint32_t)s * STAGE;
#pragma unroll
        for (int kk = 0; kk < 4; ++kk) {
            uint32_t ah[4];
            ldmx4(ah, st + aOff + (uint32_t)(kk * 32));
            uint32_t bh[2][4];
#pragma unroll
            for (int p = 0; p < 2; ++p)
                ldmx4(bh[p], st + ATILE + bOff + (uint32_t)(p * 16 * ROWB + kk * 32));
#pragma unroll
            for (int nt = 0; nt < 4; ++nt)
                mma16816(acc[nt], ah, &bh[nt >> 1][(nt & 1) * 2]);
        }

        __syncthreads();
        if (c + 3 < NC) load_chunk(c + 3, s);
        cp_commit();                     // empty groups at tail keep counts aligned
        s = (s == 2) ? 0 : s + 1;
    }

    // Epilogue: raw partial store (bias/ReLU applied at reduce in pointwise)
    const int g = lane >> 2, q2 = (lane & 3) * 2;
#pragma unroll
    for (int nt = 0; nt < 4; ++nt) {
        int col = n0 + wn * 32 + nt * 8 + q2;
        int r0 = m0 + wm * 16 + g;
        *(float2*)&out[(size_t)r0 * N + col] = make_float2(acc[nt][0], acc[nt][1]);
        *(float2*)&out[(size_t)(r0 + 8) * N + col] = make_float2(acc[nt][2], acc[nt][3]);
    }
}

// ---------------------------------------------------------------------------
// Fused per-node LSTM pointwise for BOTH nets in one launch, with
// split-K reduce + agg bias + ReLU:  x = relu(xp0 + xp1 + ab1[n] + ab2[n])
//   blockIdx.x [0,128): h-net (N=4096), [128,160): o-net (N=1024)
// ---------------------------------------------------------------------------
__global__ __launch_bounds__(256) void lstm_pointwise2(
    const float* __restrict__ xph, const float* __restrict__ b_i2h,
    const float* __restrict__ b_h2h,
    const float* __restrict__ h_in, const float* __restrict__ h_cells,
    const float* __restrict__ Wih_h, const float* __restrict__ Whh_h,
    const float* __restrict__ bias_h, const float* __restrict__ Whr_h,
    float* __restrict__ new_h, float* __restrict__ new_hc,
    const float* __restrict__ xpo, const float* __restrict__ b_i2o,
    const float* __restrict__ b_h2o,
    const float* __restrict__ o_in, const float* __restrict__ o_cells,
    const float* __restrict__ Wih_o, const float* __restrict__ Whh_o,
    const float* __restrict__ bias_o, const float* __restrict__ Whr_o,
    float* __restrict__ new_o, float* __restrict__ new_oc)
{
    __shared__ float sX[32][33];
    __shared__ float sH[32][33];
    __shared__ float sHn[32][33];
    __shared__ float sWih[32][16];
    __shared__ float sWhh[32][16];
    __shared__ float sBias[32][16];
    __shared__ float sWhr[32][4];
    __shared__ float sAggB[32];

    const int t = threadIdx.x;
    const int bx = blockIdx.x;
    const int b0 = blockIdx.y * 32;

    const float *xp0, *ab1, *ab2, *hprev, *cprev, *Wih, *Whh, *bias, *Whr;
    float *hnew, *cnew;
    int N, n0;
    if (bx < NH / 32) {
        N = NH; n0 = bx * 32;
        xp0 = xph; ab1 = b_i2h; ab2 = b_h2h; hprev = h_in; cprev = h_cells;
        Wih = Wih_h; Whh = Whh_h; bias = bias_h; Whr = Whr_h;
        hnew = new_h; cnew = new_hc;
    } else {
        N = NO; n0 = (bx - NH / 32) * 32;
        xp0 = xpo; ab1 = b_i2o; ab2 = b_h2o; hprev = o_in; cprev = o_cells;
        Wih = Wih_o; Whh = Whh_o; bias = bias_o; Whr = Whr_o;
        hnew = new_o; cnew = new_oc;
    }
    const float* xp1 = xp0 + (size_t)BB * N;   // second split-K partial
    const int B = BB;

    if (t < 128) {
        int nl = t >> 2, w = t & 3;
        ((float4*)&sWih[nl][0])[w]  = ((const float4*)Wih)[(size_t)(n0 + nl) * 4 + w];
        ((float4*)&sWhh[nl][0])[w]  = ((const float4*)Whh)[(size_t)(n0 + nl) * 4 + w];
        ((float4*)&sBias[nl][0])[w] = ((const float4*)bias)[(size_t)(n0 + nl) * 4 + w];
    }
    if (t < 32) {
        *(float4*)&sWhr[t][0] = ((const float4*)Whr)[(size_t)(n0 + t)];
        sAggB[t] = ab1[n0 + t] + ab2[n0 + t];
    }

#pragma unroll
    for (int q = 0; q < 4; ++q) {
        int idx = t + 256 * q;
        int bl = idx >> 5, nl = idx & 31;
        size_t gi = (size_t)(b0 + bl) * N + n0 + nl;
        sX[bl][nl] = xp0[gi] + xp1[gi];
        sH[bl][nl] = hprev[gi];
    }
    __syncthreads();

#pragma unroll
    for (int q = 0; q < 4; ++q) {
        int idx = t + 256 * q;
        int bl = idx & 31, nl = idx >> 5;
        int n = n0 + nl, b = b0 + bl;

        float x  = fmaxf(sX[bl][nl] + sAggB[nl], 0.f);   // reduce + bias + ReLU
        float hp = sH[bl][nl];

        float g[16];
#pragma unroll
        for (int j = 0; j < 16; ++j)
            g[j] = fmaf(x, sWih[nl][j], fmaf(hp, sWhh[nl][j], sBias[nl][j]));

        float cp[4];
        *(float4*)cp = *(const float4*)&cprev[((size_t)n * B + b) * 4];

        float cn[4];
        float hsum = 0.f;
#pragma unroll
        for (int c = 0; c < 4; ++c) {
            float ig = fsig(g[c]);
            float fg = fsig(g[4 + c]);
            float gg = ftanh(g[8 + c]);
            float og = fsig(g[12 + c]);
            float cnc = fmaf(fg, cp[c], ig * gg);
            cn[c] = cnc;
            hsum = fmaf(og * ftanh(cnc), sWhr[nl][c], hsum);
        }
        *(float4*)&cnew[((size_t)n * B + b) * 4] =
            make_float4(cn[0], cn[1], cn[2], cn[3]);
        sHn[bl][nl] = hsum;
    }
    __syncthreads();

#pragma unroll
    for (int q = 0; q < 4; ++q) {
        int idx = t + 256 * q;
        int bl = idx >> 5, nl = idx & 31;
        hnew[(size_t)(b0 + bl) * N + n0 + nl] = sHn[bl][nl];
    }
}

// ---------------------------------------------------------------------------
// Launch
// ---------------------------------------------------------------------------
extern "C" void kernel_launch(void* const* d_in, const int* in_sizes, int n_in,
                              void* d_out, int out_size)
{
    const float* i_in    = (const float*)d_in[0];
    const float* h_in    = (const float*)d_in[1];
    const float* o_in    = (const float*)d_in[2];
    const float* h_cells = (const float*)d_in[3];
    const float* o_cells = (const float*)d_in[4];
    const float* W_i2h   = (const float*)d_in[5];
    const float* b_i2h   = (const float*)d_in[6];
    const float* W_h2h   = (const float*)d_in[7];
    const float* b_h2h   = (const float*)d_in[8];
    const float* W_i2o   = (const float*)d_in[9];
    const float* b_i2o   = (const float*)d_in[10];
    const float* W_h2o   = (const float*)d_in[11];
    const float* b_h2o   = (const float*)d_in[12];
    const float* Wih_h   = (const float*)d_in[13];
    const float* Whh_h   = (const float*)d_in[14];
    const float* bias_h  = (const float*)d_in[15];
    const float* Whr_h   = (const float*)d_in[16];
    const float* Wih_o   = (const float*)d_in[17];
    const float* Whh_o   = (const float*)d_in[18];
    const float* bias_o  = (const float*)d_in[19];
    const float* Whr_o   = (const float*)d_in[20];

    float* out    = (float*)d_out;
    float* new_h  = out;
    float* new_o  = new_h + (size_t)BB * NH;
    float* new_hc = new_o + (size_t)BB * NO;
    float* new_oc = new_hc + (size_t)NH * BB * CC;

    float* inh = nullptr; float* ino = nullptr;
    cudaGetSymbolAddress((void**)&inh, g_inh);
    cudaGetSymbolAddress((void**)&ino, g_ino);

    __half *if16, *hf16, *w1hh, *w2hh, *w1oh, *w2oh;
    cudaGetSymbolAddress((void**)&if16, g_i_f16);
    cudaGetSymbolAddress((void**)&hf16, g_h_f16);
    cudaGetSymbolAddress((void**)&w1hh, g_w1h_f16);
    cudaGetSymbolAddress((void**)&w2hh, g_w2h_f16);
    cudaGetSymbolAddress((void**)&w1oh, g_w1o_f16);
    cudaGetSymbolAddress((void**)&w2oh, g_w2o_f16);

    // Fused fp16 convert: one launch covering all 6 tensors, 2 float4/thread
    cvt_all<<<(unsigned)(S5 / 512), 256>>>(
        (const float4*)i_in, (const float4*)h_in, (const float4*)W_i2h,
        (const float4*)W_h2h, (const float4*)W_i2o, (const float4*)W_h2o,
        (uint2*)if16, (uint2*)hf16,
        (uint2*)w1hh, (uint2*)w2hh, (uint2*)w1oh, (uint2*)w2oh);

    // Combined split-K2 GEMM: 1280 CTAs (2 K-halves x 640 128x64 tiles)
    constexpr int SMEM = 3 * (128 + 64) * 144;   // 3 stages x 27648B = 82944
    cudaFuncSetAttribute(gemm_f16, cudaFuncAttributeMaxDynamicSharedMemorySize, SMEM);
    gemm_f16<<<1280, 512, SMEM>>>(
        if16, hf16, w1hh, w2hh, w1oh, w2oh, inh, ino);

    // Fused pointwise for both nets (split-K reduce + agg-bias + ReLU + LSTM)
    lstm_pointwise2<<<dim3((NH + NO) / 32, BB / 32), 256>>>(
        inh, b_i2h, b_h2h, h_in, h_cells, Wih_h, Whh_h, bias_h, Whr_h,
        new_h, new_hc,
        ino, b_i2o, b_h2o, o_in, o_cells, Wih_o, Whh_o, bias_o, Whr_o,
        new_o, new_oc);
}